// round 14
// baseline (speedup 1.0000x reference)
#include <cuda_runtime.h>
#include <cuda_fp16.h>
#include <math.h>
#include <stdint.h>

// ---------------- problem constants ----------------
#define NB    1000      // B
#define NN    20        // neighbors per node
#define D_    172
#define DT_   100
#define E_    272       // D + DT
#define DK_   444       // D + DT + DE
#define KPAD  448       // padded K for W1 GEMM input
#define QK    192       // padded K (172->192); also MEMh stride
#define QTK   288       // padded K for Wqk reduction (272->288)
#define QTW   912       // QT row stride: [q~0(448) | q~1(448) | c0 c1 | pad]
#define QTN   898       // valid QT cols
#define CTW   896       // CTX row stride: [ctx0(448) | ctx1(448)]
#define WQKR  904       // Wqk rows (padded from 898)
#define NNODE 100000

#define R1    (NB*NN)    // 20000 layer-1 queries
#define ROWS1 (R1*NN)    // 400000 layer-1 kv rows

// ---------------- scratch (device globals; zero-initialized, no allocs) ----------------
__device__ __align__(16) __half g_MEMh [(size_t)NNODE * QK];    // fp16 memory, stride 192
__device__ __align__(16) __half g_QTh  [(size_t)R1 * QTW];      // q~ per query
__device__ __align__(16) __half g_CTX  [(size_t)R1 * CTW];      // per-head raw contexts
__device__ __align__(16) __half g_Afull[(size_t)R1 * KPAD];     // [O(272)|src(172)|pad4] MLP input
__device__ __align__(16) __half g_Hh   [(size_t)R1 * QK];       // pads stay 0
__device__ __align__(16) __half g_EMBh [(size_t)R1 * D_ + 64];
// weights
__device__ __align__(16) __half g_Wqk [(size_t)2 * WQKR * QTK]; // Wk transpose-scatter + bk rows
__device__ __align__(16) __half g_Wc  [(size_t)2 * WQKR * QK];  // combined Wqk @ Wq
__device__ __align__(16) __half g_Wov [(size_t)2 * E_ * CTW];   // combined Wo@Wv per head
__device__ __align__(16) __half g_W1h [(size_t)2 * D_ * KPAD];
__device__ __align__(16) __half g_W2h [(size_t)2 * D_ * QK];
__device__ float g_bc   [2 * WQKR];
__device__ float g_bOV  [2 * E_];
__device__ int   g_AM   [R1];

// ============================================================================
// fp16 tensor-core GEMM (HMMA) -- round-10 proven config; optional indexed A rows.
//   C[M,N] = A[row][K] @ W[N,K]^T + bias  (row = Aidx?Aidx[m]:m; fp32 accum)
// CTA tile 128x96, BK=32, 256 thr (warps 4m x 2n, warp tile 32x48).
// 3-stage cp.async ring, ONE __syncthreads per chunk.
// ============================================================================
#define AST 40
#define BST 40
#define A_STAGE (128 * AST)
#define B_STAGE (96 * BST)
#define HG_SMEM ((3 * (A_STAGE + B_STAGE)) * 2)   // 53760 bytes

__device__ __forceinline__ void ldsm_x4(uint32_t* r, uint32_t addr) {
    asm volatile("ldmatrix.sync.aligned.m8n8.x4.shared.b16 {%0,%1,%2,%3}, [%4];"
                 : "=r"(r[0]), "=r"(r[1]), "=r"(r[2]), "=r"(r[3]) : "r"(addr));
}
__device__ __forceinline__ void mma16816(float* d, const uint32_t* a, uint32_t b0, uint32_t b1) {
    asm volatile("mma.sync.aligned.m16n8k16.row.col.f32.f16.f16.f32 "
                 "{%0,%1,%2,%3}, {%4,%5,%6,%7}, {%8,%9}, {%0,%1,%2,%3};"
                 : "+f"(d[0]), "+f"(d[1]), "+f"(d[2]), "+f"(d[3])
                 : "r"(a[0]), "r"(a[1]), "r"(a[2]), "r"(a[3]), "r"(b0), "r"(b1));
}
__device__ __forceinline__ void cp16(uint32_t dst, const void* src, int sz) {
    asm volatile("cp.async.cg.shared.global [%0], [%1], 16, %2;"
                 :: "r"(dst), "l"(src), "r"(sz));
}

template<int HALF_OUT, int IDX>
__global__ __launch_bounds__(256)
void hgemm(const __half* __restrict__ A, int lda,
           const int* __restrict__ Aidx,
           const __half* __restrict__ W,
           const float* __restrict__ bias,
           const int* __restrict__ rowzero,
           void* __restrict__ Cout, int ldc,
           int M, int N, int K, int relu)
{
    extern __shared__ __half smem[];
    __half* sA = smem;
    __half* sB = smem + 3 * A_STAGE;

    const int tid  = threadIdx.x;
    const int lane = tid & 31, wid = tid >> 5;
    const int warp_m = wid & 3, warp_n = wid >> 2;
    const int m0 = blockIdx.y * 128;
    const int n0 = blockIdx.x * 96;
    const int nchunks = K >> 5;

    float acc[2][6][4];
    #pragma unroll
    for (int i = 0; i < 2; i++)
        #pragma unroll
        for (int j = 0; j < 6; j++)
            #pragma unroll
            for (int q = 0; q < 4; q++) acc[i][j][q] = 0.f;

    auto loadA = [&](int s, int k0) {
        #pragma unroll
        for (int c = tid; c < 512; c += 256) {
            int row = c >> 2, seg = c & 3;
            int gm = m0 + row;
            size_t ar = IDX ? (size_t)(gm < M ? Aidx[gm] : 0) : (size_t)gm;
            uint32_t dst = (uint32_t)__cvta_generic_to_shared(&sA[s * A_STAGE + row * AST + seg * 8]);
            cp16(dst, A + ar * lda + k0 + seg * 8, gm < M ? 16 : 0);
        }
    };
    auto loadB = [&](int s, int k0) {
        #pragma unroll
        for (int c = tid; c < 384; c += 256) {
            int row = c >> 2, seg = c & 3;
            int gn = n0 + row;
            uint32_t dst = (uint32_t)__cvta_generic_to_shared(&sB[s * B_STAGE + row * BST + seg * 8]);
            cp16(dst, W + (size_t)gn * K + k0 + seg * 8, gn < N ? 16 : 0);
        }
    };

    auto computeStage = [&](int s) {
        const __half* As = sA + s * A_STAGE;
        const __half* Bs = sB + s * B_STAGE;
        #pragma unroll
        for (int kk = 0; kk < 2; ++kk) {
            uint32_t afr[2][4];
            #pragma unroll
            for (int i = 0; i < 2; ++i) {
                uint32_t addr = (uint32_t)__cvta_generic_to_shared(
                    &As[(warp_m * 32 + i * 16 + (lane & 15)) * AST + kk * 16 + (lane >> 4) * 8]);
                ldsm_x4(afr[i], addr);
            }
            uint32_t bfr[3][4];
            #pragma unroll
            for (int j = 0; j < 3; ++j) {
                int nrow = warp_n * 48 + j * 16 + ((lane >> 4) << 3) + (lane & 7);
                int kcol = kk * 16 + ((lane >> 3) & 1) * 8;
                uint32_t addr = (uint32_t)__cvta_generic_to_shared(&Bs[nrow * BST + kcol]);
                ldsm_x4(bfr[j], addr);
            }
            #pragma unroll
            for (int i = 0; i < 2; ++i)
                #pragma unroll
                for (int j = 0; j < 6; ++j)
                    mma16816(acc[i][j], afr[i], bfr[j >> 1][(j & 1) * 2], bfr[j >> 1][(j & 1) * 2 + 1]);
        }
    };

    loadA(0, 0); loadB(0, 0);
    asm volatile("cp.async.commit_group;" ::: "memory");
    if (nchunks > 1) { loadA(1, 32); loadB(1, 32); }
    asm volatile("cp.async.commit_group;" ::: "memory");

    for (int c = 0; c < nchunks; ++c) {
        asm volatile("cp.async.wait_group 1;" ::: "memory");
        __syncthreads();
        if (c + 2 < nchunks) {
            int s = (c + 2) % 3;
            loadA(s, (c + 2) * 32); loadB(s, (c + 2) * 32);
        }
        asm volatile("cp.async.commit_group;" ::: "memory");
        computeStage(c % 3);
    }

    #pragma unroll
    for (int i = 0; i < 2; ++i) {
        #pragma unroll
        for (int half_ = 0; half_ < 2; ++half_) {
            int r = m0 + warp_m * 32 + i * 16 + (lane >> 2) + half_ * 8;
            if (r >= M) continue;
            int rz = rowzero ? rowzero[r] : 0;
            #pragma unroll
            for (int j = 0; j < 6; ++j) {
                int col = n0 + warp_n * 48 + j * 8 + (lane & 3) * 2;
                if (col < N) {
                    float v0 = acc[i][j][half_ * 2]     + bias[col];
                    float v1 = acc[i][j][half_ * 2 + 1] + bias[col + 1];
                    if (rz) { v0 = 0.f; v1 = 0.f; }
                    if (relu) { v0 = fmaxf(v0, 0.f); v1 = fmaxf(v1, 0.f); }
                    if (HALF_OUT) {
                        *(__half2*)((__half*)Cout + (size_t)r * ldc + col) =
                            __floats2half2_rn(v0, v1);
                    } else {
                        float* cp = (float*)Cout + (size_t)r * ldc + col;
                        cp[0] = v0; cp[1] = v1;
                    }
                }
            }
        }
    }
}

// ---------------- fused conversion: W1, W2 -> fp16 padded; memory -> MEMh ----------------
struct CvtJob { int srcSel; long srcOff; long N; int Ksrc; int Kcopy; int KP; int dstSel; long dstOff; };
__constant__ CvtJob c_jobs[5] = {
    {0, 0,            D_,    DK_, DK_, KPAD, 0, 0},
    {0, (long)D_*DK_, D_,    DK_, DK_, KPAD, 0, (long)D_*KPAD},
    {1, 0,            D_,    D_,  D_,  QK,   1, 0},
    {1, (long)D_*D_,  D_,    D_,  D_,  QK,   1, (long)D_*QK},
    {2, 0,            NNODE, D_,  D_,  QK,   2, 0},
};

__global__ void convert_all(const float* __restrict__ W1, const float* __restrict__ W2,
                            const float* __restrict__ mem)
{
    CvtJob j = c_jobs[blockIdx.y];
    const float* srcTab[3] = {W1, W2, mem};
    __half* dstTab[3] = {g_W1h, g_W2h, g_MEMh};
    const float* src = srcTab[j.srcSel] + j.srcOff;
    __half* dst = dstTab[j.dstSel] + j.dstOff;
    long total = j.N * j.KP;
    for (long i = (long)blockIdx.x * blockDim.x + threadIdx.x; i < total;
         i += (long)gridDim.x * blockDim.x) {
        int k = (int)(i % j.KP);
        long n = i / j.KP;
        dst[i] = __float2half(k < j.Kcopy ? src[n * j.Ksrc + k] : 0.f);
    }
}

// ---------------- Wqk[l][n][k]: transpose-scatter of Wk + bk rows ----------------
__global__ void build_wqk(const float* __restrict__ Wk, const float* __restrict__ bk)
{
    int l = blockIdx.y;
    __half* dst = g_Wqk + (size_t)l * WQKR * QTK;
    const long total = (long)WQKR * QTK;
    for (long i = (long)blockIdx.x * blockDim.x + threadIdx.x; i < total;
         i += (long)gridDim.x * blockDim.x) {
        int n = (int)(i / QTK), k = (int)(i % QTK);
        float v = 0.f;
        if (n < 444) {
            if (k < 136) v = Wk[((size_t)l * E_ + k) * DK_ + n];
        } else if (n >= 448 && n < 892) {
            if (k >= 136 && k < E_) v = Wk[((size_t)l * E_ + k) * DK_ + (n - 448)];
        } else if (n == 896) {
            if (k < 136) v = bk[l * E_ + k];
        } else if (n == 897) {
            if (k >= 136 && k < E_) v = bk[l * E_ + k];
        }
        dst[i] = __float2half(v);
    }
}

// ---------------- prep_qbias: bc = Wqk @ cq (cq recomputed in-block) + bov ----------------
__global__ void prep_qbias(const float* __restrict__ Wq, const float* __restrict__ bq,
                           const float* __restrict__ b_time,
                           const float* __restrict__ Wo, const float* __restrict__ bv,
                           const float* __restrict__ bo)
{
    int l = blockIdx.y, b = blockIdx.x;
    int tid = threadIdx.x, lane = tid & 31, w = tid >> 5;

    if (b == 9) {   // bov: b_ov[l][m] = Wo[l][m]·bv[l] + bo[l][m]
        for (int m = w; m < E_; m += 8) {
            const float* wo = Wo + ((size_t)l * E_ + m) * E_;
            float s = 0.f;
            for (int e = lane; e < E_; e += 32) s += wo[e] * bv[l * E_ + e];
            #pragma unroll
            for (int o = 16; o; o >>= 1) s += __shfl_xor_sync(0xffffffffu, s, o);
            if (lane == 0) g_bOV[l * E_ + m] = s + bo[l * E_ + m];
        }
        return;
    }

    __shared__ float cb[DT_];
    __shared__ float cq[E_];
    for (int j = tid; j < DT_; j += 256) cb[j] = cosf(b_time[j]);
    __syncthreads();
    for (int e = tid; e < E_; e += 256) {
        float s = bq[l * E_ + e];
        const float* wr = Wq + (size_t)l * E_ * E_ + (size_t)e * E_ + D_;
        #pragma unroll 4
        for (int j = 0; j < DT_; j++) s += cb[j] * wr[j];
        cq[e] = s;
    }
    __syncthreads();

    for (int n = b * 8 + w; n < QTN; n += 72) {
        const __half* row = g_Wqk + (size_t)l * WQKR * QTK + (size_t)n * QTK;
        float s = 0.f;
        for (int e = lane; e < E_; e += 32) s += __half2float(row[e]) * cq[e];
        #pragma unroll
        for (int o = 16; o; o >>= 1) s += __shfl_xor_sync(0xffffffffu, s, o);
        if (lane == 0) g_bc[l * WQKR + n] = s;
    }
}

// ---------------- build_wc: Wc[l][n][k] = sum_e Wqk[l][n][e] * Wq[l][e][k] (k<172) ----
__global__ void build_wc(const float* __restrict__ Wq)
{
    int n = blockIdx.x, l = blockIdx.y;
    int k = threadIdx.x;   // 192 threads
    __shared__ float sq[E_];
    for (int e = k; e < E_; e += 192)
        sq[e] = __half2float(g_Wqk[(size_t)l * WQKR * QTK + (size_t)n * QTK + e]);
    __syncthreads();
    float acc = 0.f;
    if (k < D_) {
        const float* wq = Wq + (size_t)l * E_ * E_ + k;
        #pragma unroll 4
        for (int e = 0; e < E_; e++) acc += sq[e] * wq[(size_t)e * E_];
    }
    g_Wc[((size_t)l * WQKR + n) * QK + k] = __float2half(acc);
}

// ---------------- Wov[l][m][h*448+j] = sum_d Wo[l][m][h*136+d] * Wv[l][h*136+d][j] ----
__global__ void build_wov(const float* __restrict__ Wo, const float* __restrict__ Wv)
{
    int m = blockIdx.x, h = blockIdx.y, l = blockIdx.z;
    __shared__ float wo[136];
    for (int d = threadIdx.x; d < 136; d += 128)
        wo[d] = Wo[((size_t)l * E_ + m) * E_ + h * 136 + d];
    __syncthreads();
    for (int j = threadIdx.x; j < 448; j += 128) {
        float s = 0.f;
        if (j < 444) {
            const float* wv = Wv + ((size_t)l * E_ + h * 136) * DK_ + j;
            #pragma unroll 4
            for (int d = 0; d < 136; d++) s += wo[d] * wv[(size_t)d * DK_];
        }
        g_Wov[((size_t)l * E_ + m) * CTW + h * 448 + j] = __float2half(s);
    }
}

// ---------------- copy gathered src rows into MLP-input cols [272, 444) ----------------
__global__ void copy_src_idx(const int* __restrict__ idx, int rows)
{
    long total = (long)rows * D_;
    for (long i = (long)blockIdx.x*blockDim.x + threadIdx.x; i < total;
         i += (long)gridDim.x * blockDim.x) {
        int r = (int)(i / D_);
        int k = (int)(i % D_);
        g_Afull[(size_t)r * KPAD + E_ + k] = g_MEMh[(size_t)idx[r] * QK + k];
    }
}

// ============================================================================
// fused attention (round-12 proven): block per query.
// ============================================================================
template<int GATHER>
__global__ __launch_bounds__(128)
void fused_attn(const __half* __restrict__ memh, int mstride,
                const int* __restrict__ nbrs,
                const float* __restrict__ edgef,
                const int* __restrict__ eidx,
                const float* __restrict__ etime,
                const float* __restrict__ ts, int ts_div,
                const float* __restrict__ w_time, const float* __restrict__ b_time,
                const __half* __restrict__ QT,
                __half* __restrict__ CTX, int* __restrict__ AM, int R)
{
    __shared__ __half skv[NN][448];
    __shared__ float sc[2][NN];
    __shared__ float aw[2][NN];

    int r = blockIdx.x;
    if (r >= R) return;
    int tid = threadIdx.x, lane = tid & 31, w = tid >> 5;
    float tsr = ts[r / ts_div];
    const long kvbase = (long)r * NN;

    for (int idx = tid; idx < NN * 448; idx += 128) {
        int n = idx / 448, j = idx - n * 448;
        long kvrow = kvbase + n;
        float v;
        if (j < D_) {
            long src = GATHER ? (long)nbrs[kvrow] : kvrow;
            v = __half2float(memh[src * mstride + j]);
        } else if (j < E_) {
            int q = j - D_;
            float dt = tsr - etime[kvrow];
            v = __cosf(dt * w_time[q] + b_time[q]);
        } else if (j < DK_) {
            v = edgef[(size_t)eidx[kvrow] * D_ + (j - E_)];
        } else v = 0.f;
        skv[n][j] = __float2half(v);
    }
    __syncthreads();

    const __half* qtr = QT + (size_t)r * QTW;
    float q0[14], q1[14];
    #pragma unroll
    for (int i = 0; i < 14; ++i) {
        int j = lane + i * 32;
        q0[i] = __half2float(qtr[j]);
        q1[i] = __half2float(qtr[448 + j]);
    }
    for (int p = w; p < 2 * NN; p += 4) {
        int n = p >> 1, h = p & 1;
        float s = 0.f;
        #pragma unroll
        for (int i = 0; i < 14; ++i) {
            float kv = __half2float(skv[n][lane + i * 32]);
            s += (h ? q1[i] : q0[i]) * kv;
        }
        #pragma unroll
        for (int o = 16; o; o >>= 1) s += __shfl_xor_sync(0xffffffffu, s, o);
        if (lane == 0) sc[h][n] = s;
    }
    __syncthreads();

    if (tid < 2) {
        int h = tid;
        float ch = __half2float(qtr[896 + h]);
        const float scale = rsqrtf(136.f);
        float v[NN];
        float mx = -3.4e38f;
        int allm = 1;
        #pragma unroll
        for (int n = 0; n < NN; n++) {
            int masked = (nbrs[kvbase + n] == 0);
            float s = masked ? -1e9f : (sc[h][n] + ch) * scale;
            if (!masked) allm = 0;
            v[n] = s;
            mx = fmaxf(mx, s);
        }
        float ssum = 0.f;
        #pragma unroll
        for (int n = 0; n < NN; n++) { float e = __expf(v[n] - mx); v[n] = e; ssum += e; }
        float inv = 1.f / ssum;
        #pragma unroll
        for (int n = 0; n < NN; n++) aw[h][n] = v[n] * inv;
        if (h == 0) AM[r] = allm;
    }
    __syncthreads();

    for (int j = tid; j < 448; j += 128) {
        float c0 = 0.f, c1 = 0.f;
        #pragma unroll
        for (int n = 0; n < NN; n++) {
            float kv = __half2float(skv[n][j]);
            c0 += aw[0][n] * kv;
            c1 += aw[1][n] * kv;
        }
        CTX[(size_t)r * CTW + j]       = __float2half(c0);
        CTX[(size_t)r * CTW + 448 + j] = __float2half(c1);
    }
}

// ---------------- host helpers ----------------
static void launch_hgemm_h(const __half* A, int lda, const __half* W, const float* bias,
                           const int* rz, __half* C, int ldc, int M, int N, int K, int relu)
{
    dim3 grid((N + 95)/96, (M + 127)/128);
    hgemm<1,0><<<grid, 256, HG_SMEM>>>(A, lda, nullptr, W, bias, rz, (void*)C, ldc, M, N, K, relu);
}
static void launch_hgemm_idx(const __half* A, int lda, const int* Aidx,
                             const __half* W, const float* bias,
                             __half* C, int ldc, int M, int N, int K)
{
    dim3 grid((N + 95)/96, (M + 127)/128);
    hgemm<1,1><<<grid, 256, HG_SMEM>>>(A, lda, Aidx, W, bias, nullptr, (void*)C, ldc, M, N, K, 0);
}
static void launch_hgemm_f(const __half* A, int lda, const __half* W, const float* bias,
                           const int* rz, float* C, int ldc, int M, int N, int K, int relu)
{
    dim3 grid((N + 95)/96, (M + 127)/128);
    hgemm<0,0><<<grid, 256, HG_SMEM>>>(A, lda, nullptr, W, bias, rz, (void*)C, ldc, M, N, K, relu);
}

extern "C" void kernel_launch(void* const* d_in, const int* in_sizes, int n_in,
                              void* d_out, int out_size)
{
    const float* memory = (const float*)d_in[0];
    const float* edgef  = (const float*)d_in[1];
    const int*   srcn   = (const int*)  d_in[2];
    const float* ts     = (const float*)d_in[3];
    const int*   nb1    = (const int*)  d_in[4];
    const int*   ei1    = (const int*)  d_in[5];
    const float* et1    = (const float*)d_in[6];
    const int*   nb2    = (const int*)  d_in[7];
    const int*   ei2    = (const int*)  d_in[8];
    const float* et2    = (const float*)d_in[9];
    const float* w_time = (const float*)d_in[10];
    const float* b_time = (const float*)d_in[11];
    const float* Wq = (const float*)d_in[12];
    const float* bq = (const float*)d_in[13];
    const float* Wk = (const float*)d_in[14];
    const float* bk = (const float*)d_in[15];
    const float* Wv = (const float*)d_in[16];
    const float* bv = (const float*)d_in[17];
    const float* Wo = (const float*)d_in[18];
    const float* bo = (const float*)d_in[19];
    const float* W1 = (const float*)d_in[20];
    const float* b1 = (const float*)d_in[21];
    const float* W2 = (const float*)d_in[22];
    const float* b2 = (const float*)d_in[23];
    float* out = (float*)d_out;

    __half *pMEMh, *pQT, *pCTX, *pAfull, *pHh, *pEMBh;
    __half *pWc, *pWov, *pW1h, *pW2h;
    float *pbc, *pbOV;
    int* pAM;
    cudaGetSymbolAddress((void**)&pMEMh,  g_MEMh);
    cudaGetSymbolAddress((void**)&pQT,    g_QTh);
    cudaGetSymbolAddress((void**)&pCTX,   g_CTX);
    cudaGetSymbolAddress((void**)&pAfull, g_Afull);
    cudaGetSymbolAddress((void**)&pHh,    g_Hh);
    cudaGetSymbolAddress((void**)&pEMBh,  g_EMBh);
    cudaGetSymbolAddress((void**)&pWc,    g_Wc);
    cudaGetSymbolAddress((void**)&pWov,   g_Wov);
    cudaGetSymbolAddress((void**)&pW1h,   g_W1h);
    cudaGetSymbolAddress((void**)&pW2h,   g_W2h);
    cudaGetSymbolAddress((void**)&pbc,    g_bc);
    cudaGetSymbolAddress((void**)&pbOV,   g_bOV);
    cudaGetSymbolAddress((void**)&pAM,    g_AM);

    cudaFuncSetAttribute((const void*)hgemm<1,0>, cudaFuncAttributeMaxDynamicSharedMemorySize, HG_SMEM);
    cudaFuncSetAttribute((const void*)hgemm<1,1>, cudaFuncAttributeMaxDynamicSharedMemorySize, HG_SMEM);
    cudaFuncSetAttribute((const void*)hgemm<0,0>, cudaFuncAttributeMaxDynamicSharedMemorySize, HG_SMEM);

    const size_t WCs = (size_t)WQKR*QK, WOVs = (size_t)E_*CTW,
                 W1s = (size_t)D_*KPAD, W2s = (size_t)D_*QK;

    // ---- prologue (5 launches) ----
    convert_all<<<dim3(512, 5), 256>>>(W1, W2, memory);                          // 1
    build_wqk<<<dim3(256, 2), 256>>>(Wk, bk);                                    // 2
    prep_qbias<<<dim3(10, 2), 256>>>(Wq, bq, b_time, Wo, bv, bo);                // 3
    build_wc<<<dim3(WQKR, 2), QK>>>(Wq);                                         // 4

    // ================= Layer 1 =================
    launch_hgemm_idx(pMEMh, QK, nb1, pWc, pbc, pQT, QTW, R1, QTN, QK);           // 5
    fused_attn<1><<<R1, 128>>>(pMEMh, QK, nb2, edgef, ei2, et2, ts, NN,          // 6 <- profiled
                               w_time, b_time, pQT, pCTX, pAM, R1);
    build_wov<<<dim3(E_, 2, 2), 128>>>(Wo, Wv);                                  // 7
    launch_hgemm_h(pCTX, CTW, pWov, pbOV, pAM, pAfull, KPAD, R1, E_, CTW, 0);    // 8
    copy_src_idx<<<(R1*D_ + 255)/256, 256>>>(nb1, R1);                           // 9
    launch_hgemm_h(pAfull, KPAD, pW1h, b1, nullptr, pHh, QK, R1, D_, KPAD, 1);   // 10
    launch_hgemm_h(pHh, QK, pW2h, b2, nullptr, pEMBh, D_, R1, D_, QK, 0);        // 11

    // ================= Layer 2 =================
    launch_hgemm_idx(pMEMh, QK, srcn, pWc + WCs, pbc + WQKR, pQT, QTW, NB, QTN, QK); // 12
    fused_attn<0><<<NB, 128>>>(pEMBh, D_, nb1, edgef, ei1, et1, ts, 1,           // 13
                               w_time, b_time, pQT, pCTX, pAM, NB);
    launch_hgemm_h(pCTX, CTW, pWov + WOVs, pbOV + E_, pAM, pAfull, KPAD, NB, E_, CTW, 0); // 14
    copy_src_idx<<<(NB*D_ + 255)/256, 256>>>(srcn, NB);                          // 15
    launch_hgemm_h(pAfull, KPAD, pW1h + W1s, b1 + D_, nullptr, pHh, QK, NB, D_, KPAD, 1); // 16
    launch_hgemm_f(pHh, QK, pW2h + W2s, b2 + D_, nullptr, out, D_, NB, D_, QK, 0);        // 17
}

// round 15
// speedup vs baseline: 1.0142x; 1.0142x over previous
#include <cuda_runtime.h>
#include <cuda_fp16.h>
#include <math.h>
#include <stdint.h>

// ---------------- problem constants ----------------
#define NB    1000      // B
#define NN    20        // neighbors per node
#define D_    172
#define DT_   100
#define E_    272       // D + DT
#define DK_   444       // D + DT + DE
#define KPAD  448       // padded K for W1 GEMM input
#define QK    192       // padded K (172->192); also MEMh/SRCh stride
#define QTK   288       // padded K for Wqk reduction (272->288)
#define QTW   912       // QT row stride: [q~0(448) | q~1(448) | c0 c1 | pad]
#define QTN   898       // valid QT cols
#define CTW   896       // CTX row stride: [ctx0(448) | ctx1(448)]
#define WQKR  904       // Wqk rows (padded from 898)
#define NNODE 100000

#define R1    (NB*NN)    // 20000 layer-1 queries

// ---------------- scratch (device globals; zero-initialized, no allocs) ----------------
__device__ __align__(16) __half g_MEMh [(size_t)NNODE * QK];    // fp16 memory, stride 192
__device__ __align__(16) __half g_SRCh [(size_t)R1 * QK];       // gathered src rows
__device__ __align__(16) __half g_QTh  [(size_t)R1 * QTW];      // q~ per query
__device__ __align__(16) __half g_CTX  [(size_t)R1 * CTW];      // per-head raw contexts
__device__ __align__(16) __half g_Afull[(size_t)R1 * KPAD];     // [O(272)|src(172)|pad4] MLP input
__device__ __align__(16) __half g_Hh   [(size_t)R1 * QK];       // pads stay 0
__device__ __align__(16) __half g_EMBh [(size_t)R1 * D_ + 64];
// weights
__device__ __align__(16) __half g_Wqk [(size_t)2 * WQKR * QTK]; // Wk transpose-scatter + bk rows
__device__ __align__(16) __half g_WqT [(size_t)2 * QK * QTK];   // Wq transposed [192][288]
__device__ __align__(16) __half g_Wc  [(size_t)2 * WQKR * QK];  // combined Wqk @ Wq
__device__ __align__(16) __half g_Wov [(size_t)2 * E_ * CTW];   // combined Wo@Wv per head
__device__ __align__(16) __half g_W1h [(size_t)2 * D_ * KPAD];
__device__ __align__(16) __half g_W2h [(size_t)2 * D_ * QK];
__device__ float g_bc   [2 * WQKR];
__device__ float g_bOV  [2 * E_];
__device__ float g_zero [1024];         // stays 0
__device__ int   g_AM   [R1];

// ============================================================================
// fp16 tensor-core GEMM (HMMA) -- round-10 proven config (1407us-era baseline):
//   C[M,N] = A[M,K] @ W[N,K]^T + bias  (fp32 accum; fp16/fp32 out, relu, rowzero)
// CTA tile 128x96, BK=32, 256 thr (warps 4m x 2n, warp tile 32x48).
// 3-stage cp.async ring, ONE __syncthreads per chunk.
// ============================================================================
#define AST 40
#define BST 40
#define A_STAGE (128 * AST)
#define B_STAGE (96 * BST)
#define HG_SMEM ((3 * (A_STAGE + B_STAGE)) * 2)   // 53760 bytes

__device__ __forceinline__ void ldsm_x4(uint32_t* r, uint32_t addr) {
    asm volatile("ldmatrix.sync.aligned.m8n8.x4.shared.b16 {%0,%1,%2,%3}, [%4];"
                 : "=r"(r[0]), "=r"(r[1]), "=r"(r[2]), "=r"(r[3]) : "r"(addr));
}
__device__ __forceinline__ void mma16816(float* d, const uint32_t* a, uint32_t b0, uint32_t b1) {
    asm volatile("mma.sync.aligned.m16n8k16.row.col.f32.f16.f16.f32 "
                 "{%0,%1,%2,%3}, {%4,%5,%6,%7}, {%8,%9}, {%0,%1,%2,%3};"
                 : "+f"(d[0]), "+f"(d[1]), "+f"(d[2]), "+f"(d[3])
                 : "r"(a[0]), "r"(a[1]), "r"(a[2]), "r"(a[3]), "r"(b0), "r"(b1));
}
__device__ __forceinline__ void cp16(uint32_t dst, const void* src, int sz) {
    asm volatile("cp.async.cg.shared.global [%0], [%1], 16, %2;"
                 :: "r"(dst), "l"(src), "r"(sz));
}

template<int HALF_OUT>
__global__ __launch_bounds__(256)
void hgemm(const __half* __restrict__ A, int lda,
           const __half* __restrict__ W,
           const float* __restrict__ bias,
           const int* __restrict__ rowzero,
           void* __restrict__ Cout, int ldc,
           int M, int N, int K, int relu)
{
    extern __shared__ __half smem[];
    __half* sA = smem;
    __half* sB = smem + 3 * A_STAGE;

    const int tid  = threadIdx.x;
    const int lane = tid & 31, wid = tid >> 5;
    const int warp_m = wid & 3, warp_n = wid >> 2;
    const int m0 = blockIdx.y * 128;
    const int n0 = blockIdx.x * 96;
    const int nchunks = K >> 5;

    float acc[2][6][4];
    #pragma unroll
    for (int i = 0; i < 2; i++)
        #pragma unroll
        for (int j = 0; j < 6; j++)
            #pragma unroll
            for (int q = 0; q < 4; q++) acc[i][j][q] = 0.f;

    auto loadA = [&](int s, int k0) {
        #pragma unroll
        for (int c = tid; c < 512; c += 256) {
            int row = c >> 2, seg = c & 3;
            int gm = m0 + row;
            uint32_t dst = (uint32_t)__cvta_generic_to_shared(&sA[s * A_STAGE + row * AST + seg * 8]);
            cp16(dst, A + (size_t)gm * lda + k0 + seg * 8, gm < M ? 16 : 0);
        }
    };
    auto loadB = [&](int s, int k0) {
        #pragma unroll
        for (int c = tid; c < 384; c += 256) {
            int row = c >> 2, seg = c & 3;
            int gn = n0 + row;
            uint32_t dst = (uint32_t)__cvta_generic_to_shared(&sB[s * B_STAGE + row * BST + seg * 8]);
            cp16(dst, W + (size_t)gn * K + k0 + seg * 8, gn < N ? 16 : 0);
        }
    };

    auto computeStage = [&](int s) {
        const __half* As = sA + s * A_STAGE;
        const __half* Bs = sB + s * B_STAGE;
        #pragma unroll
        for (int kk = 0; kk < 2; ++kk) {
            uint32_t afr[2][4];
            #pragma unroll
            for (int i = 0; i < 2; ++i) {
                uint32_t addr = (uint32_t)__cvta_generic_to_shared(
                    &As[(warp_m * 32 + i * 16 + (lane & 15)) * AST + kk * 16 + (lane >> 4) * 8]);
                ldsm_x4(afr[i], addr);
            }
            uint32_t bfr[3][4];
            #pragma unroll
            for (int j = 0; j < 3; ++j) {
                int nrow = warp_n * 48 + j * 16 + ((lane >> 4) << 3) + (lane & 7);
                int kcol = kk * 16 + ((lane >> 3) & 1) * 8;
                uint32_t addr = (uint32_t)__cvta_generic_to_shared(&Bs[nrow * BST + kcol]);
                ldsm_x4(bfr[j], addr);
            }
            #pragma unroll
            for (int i = 0; i < 2; ++i)
                #pragma unroll
                for (int j = 0; j < 6; ++j)
                    mma16816(acc[i][j], afr[i], bfr[j >> 1][(j & 1) * 2], bfr[j >> 1][(j & 1) * 2 + 1]);
        }
    };

    loadA(0, 0); loadB(0, 0);
    asm volatile("cp.async.commit_group;" ::: "memory");
    if (nchunks > 1) { loadA(1, 32); loadB(1, 32); }
    asm volatile("cp.async.commit_group;" ::: "memory");

    for (int c = 0; c < nchunks; ++c) {
        asm volatile("cp.async.wait_group 1;" ::: "memory");
        __syncthreads();
        if (c + 2 < nchunks) {
            int s = (c + 2) % 3;
            loadA(s, (c + 2) * 32); loadB(s, (c + 2) * 32);
        }
        asm volatile("cp.async.commit_group;" ::: "memory");
        computeStage(c % 3);
    }

    #pragma unroll
    for (int i = 0; i < 2; ++i) {
        #pragma unroll
        for (int half_ = 0; half_ < 2; ++half_) {
            int r = m0 + warp_m * 32 + i * 16 + (lane >> 2) + half_ * 8;
            if (r >= M) continue;
            int rz = rowzero ? rowzero[r] : 0;
            #pragma unroll
            for (int j = 0; j < 6; ++j) {
                int col = n0 + warp_n * 48 + j * 8 + (lane & 3) * 2;
                if (col < N) {
                    float v0 = acc[i][j][half_ * 2]     + bias[col];
                    float v1 = acc[i][j][half_ * 2 + 1] + bias[col + 1];
                    if (rz) { v0 = 0.f; v1 = 0.f; }
                    if (relu) { v0 = fmaxf(v0, 0.f); v1 = fmaxf(v1, 0.f); }
                    if (HALF_OUT) {
                        *(__half2*)((__half*)Cout + (size_t)r * ldc + col) =
                            __floats2half2_rn(v0, v1);
                    } else {
                        float* cp = (float*)Cout + (size_t)r * ldc + col;
                        cp[0] = v0; cp[1] = v1;
                    }
                }
            }
        }
    }
}

// ---------------- fused conversion: W1, W2 -> fp16 padded; memory -> MEMh ----------------
struct CvtJob { int srcSel; long srcOff; long N; int Ksrc; int Kcopy; int KP; int dstSel; long dstOff; };
__constant__ CvtJob c_jobs[5] = {
    {0, 0,            D_,    DK_, DK_, KPAD, 0, 0},
    {0, (long)D_*DK_, D_,    DK_, DK_, KPAD, 0, (long)D_*KPAD},
    {1, 0,            D_,    D_,  D_,  QK,   1, 0},
    {1, (long)D_*D_,  D_,    D_,  D_,  QK,   1, (long)D_*QK},
    {2, 0,            NNODE, D_,  D_,  QK,   2, 0},
};

__global__ void convert_all(const float* __restrict__ W1, const float* __restrict__ W2,
                            const float* __restrict__ mem)
{
    CvtJob j = c_jobs[blockIdx.y];
    const float* srcTab[3] = {W1, W2, mem};
    __half* dstTab[3] = {g_W1h, g_W2h, g_MEMh};
    const float* src = srcTab[j.srcSel] + j.srcOff;
    __half* dst = dstTab[j.dstSel] + j.dstOff;
    long total = j.N * j.KP;
    for (long i = (long)blockIdx.x * blockDim.x + threadIdx.x; i < total;
         i += (long)gridDim.x * blockDim.x) {
        int k = (int)(i % j.KP);
        long n = i / j.KP;
        dst[i] = __float2half(k < j.Kcopy ? src[n * j.Ksrc + k] : 0.f);
    }
}

// ---------------- Wqk[l][n][k]: transpose-scatter of Wk + bk rows ----------------
__global__ void build_wqk(const float* __restrict__ Wk, const float* __restrict__ bk)
{
    int l = blockIdx.y;
    __half* dst = g_Wqk + (size_t)l * WQKR * QTK;
    const long total = (long)WQKR * QTK;
    for (long i = (long)blockIdx.x * blockDim.x + threadIdx.x; i < total;
         i += (long)gridDim.x * blockDim.x) {
        int n = (int)(i / QTK), k = (int)(i % QTK);
        float v = 0.f;
        if (n < 444) {
            if (k < 136) v = Wk[((size_t)l * E_ + k) * DK_ + n];
        } else if (n >= 448 && n < 892) {
            if (k >= 136 && k < E_) v = Wk[((size_t)l * E_ + k) * DK_ + (n - 448)];
        } else if (n == 896) {
            if (k < 136) v = bk[l * E_ + k];
        } else if (n == 897) {
            if (k >= 136 && k < E_) v = bk[l * E_ + k];
        }
        dst[i] = __float2half(v);
    }
}

// ---------------- WqT[l][k][e] = Wq[l][e][k]  (k<172, e<272; pads stay 0) ----------------
__global__ void transpose_wq(const float* __restrict__ Wq)
{
    int l = blockIdx.y;
    const long total = (long)D_ * E_;
    for (long i = (long)blockIdx.x * blockDim.x + threadIdx.x; i < total;
         i += (long)gridDim.x * blockDim.x) {
        int k = (int)(i / E_), e = (int)(i % E_);
        g_WqT[((size_t)l * QK + k) * QTK + e] =
            __float2half(Wq[((size_t)l * E_ + e) * E_ + k]);
    }
}

// ---------------- prep_qbias: bc = Wqk @ cq (cq recomputed in-block) + bov ----------------
__global__ void prep_qbias(const float* __restrict__ Wq, const float* __restrict__ bq,
                           const float* __restrict__ b_time,
                           const float* __restrict__ Wo, const float* __restrict__ bv,
                           const float* __restrict__ bo)
{
    int l = blockIdx.y, b = blockIdx.x;
    int tid = threadIdx.x, lane = tid & 31, w = tid >> 5;

    if (b == 9) {   // bov: b_ov[l][m] = Wo[l][m]·bv[l] + bo[l][m]
        for (int m = w; m < E_; m += 8) {
            const float* wo = Wo + ((size_t)l * E_ + m) * E_;
            float s = 0.f;
            for (int e = lane; e < E_; e += 32) s += wo[e] * bv[l * E_ + e];
            #pragma unroll
            for (int o = 16; o; o >>= 1) s += __shfl_xor_sync(0xffffffffu, s, o);
            if (lane == 0) g_bOV[l * E_ + m] = s + bo[l * E_ + m];
        }
        return;
    }

    __shared__ float cb[DT_];
    __shared__ float cq[E_];
    for (int j = tid; j < DT_; j += 256) cb[j] = cosf(b_time[j]);
    __syncthreads();
    for (int e = tid; e < E_; e += 256) {
        float s = bq[l * E_ + e];
        const float* wr = Wq + (size_t)l * E_ * E_ + (size_t)e * E_ + D_;
        #pragma unroll 4
        for (int j = 0; j < DT_; j++) s += cb[j] * wr[j];
        cq[e] = s;
    }
    __syncthreads();

    for (int n = b * 8 + w; n < QTN; n += 72) {
        const __half* row = g_Wqk + (size_t)l * WQKR * QTK + (size_t)n * QTK;
        float s = 0.f;
        for (int e = lane; e < E_; e += 32) s += __half2float(row[e]) * cq[e];
        #pragma unroll
        for (int o = 16; o; o >>= 1) s += __shfl_xor_sync(0xffffffffu, s, o);
        if (lane == 0) g_bc[l * WQKR + n] = s;
    }
}

// ---------------- Wov[l][m][h*448+j] = sum_d Wo[l][m][h*136+d] * Wv[l][h*136+d][j] ----
__global__ void build_wov(const float* __restrict__ Wo, const float* __restrict__ Wv)
{
    int m = blockIdx.x, h = blockIdx.y, l = blockIdx.z;
    __shared__ float wo[136];
    for (int d = threadIdx.x; d < 136; d += 128)
        wo[d] = Wo[((size_t)l * E_ + m) * E_ + h * 136 + d];
    __syncthreads();
    for (int j = threadIdx.x; j < 448; j += 128) {
        float s = 0.f;
        if (j < 444) {
            const float* wv = Wv + ((size_t)l * E_ + h * 136) * DK_ + j;
            #pragma unroll 4
            for (int d = 0; d < 136; d++) s += wo[d] * wv[(size_t)d * DK_];
        }
        g_Wov[((size_t)l * E_ + m) * CTW + h * 448 + j] = __float2half(s);
    }
}

// ---------------- fp16 row gather from g_MEMh (both stride QK) ----------------
__global__ void gather16(const int* __restrict__ idx, __half* __restrict__ dst, int rows)
{
    long total = (long)rows * 24;
    for (long i = (long)blockIdx.x*blockDim.x + threadIdx.x; i < total;
         i += (long)gridDim.x * blockDim.x) {
        int r = (int)(i / 24);
        int s = (int)(i % 24);
        ((uint4*)(dst + (size_t)r * QK))[s] =
            ((const uint4*)(g_MEMh + (size_t)idx[r] * QK))[s];
    }
}

// ---------------- copy SRC rows into MLP-input cols [272, 444) ----------------
__global__ void copy_src(int rows)
{
    long total = (long)rows * D_;
    for (long i = (long)blockIdx.x*blockDim.x + threadIdx.x; i < total;
         i += (long)gridDim.x * blockDim.x) {
        int r = (int)(i / D_);
        int k = (int)(i % D_);
        g_Afull[(size_t)r * KPAD + E_ + k] = g_SRCh[(size_t)r * QK + k];
    }
}

// ============================================================================
// fused attention (round-12 proven): block per query.
// ============================================================================
template<int GATHER>
__global__ __launch_bounds__(128)
void fused_attn(const __half* __restrict__ memh, int mstride,
                const int* __restrict__ nbrs,
                const float* __restrict__ edgef,
                const int* __restrict__ eidx,
                const float* __restrict__ etime,
                const float* __restrict__ ts, int ts_div,
                const float* __restrict__ w_time, const float* __restrict__ b_time,
                const __half* __restrict__ QT,
                __half* __restrict__ CTX, int* __restrict__ AM, int R)
{
    __shared__ __half skv[NN][448];
    __shared__ float sc[2][NN];
    __shared__ float aw[2][NN];

    int r = blockIdx.x;
    if (r >= R) return;
    int tid = threadIdx.x, lane = tid & 31, w = tid >> 5;
    float tsr = ts[r / ts_div];
    const long kvbase = (long)r * NN;

    for (int idx = tid; idx < NN * 448; idx += 128) {
        int n = idx / 448, j = idx - n * 448;
        long kvrow = kvbase + n;
        float v;
        if (j < D_) {
            long src = GATHER ? (long)nbrs[kvrow] : kvrow;
            v = __half2float(memh[src * mstride + j]);
        } else if (j < E_) {
            int q = j - D_;
            float dt = tsr - etime[kvrow];
            v = __cosf(dt * w_time[q] + b_time[q]);
        } else if (j < DK_) {
            v = edgef[(size_t)eidx[kvrow] * D_ + (j - E_)];
        } else v = 0.f;
        skv[n][j] = __float2half(v);
    }
    __syncthreads();

    const __half* qtr = QT + (size_t)r * QTW;
    float q0[14], q1[14];
    #pragma unroll
    for (int i = 0; i < 14; ++i) {
        int j = lane + i * 32;
        q0[i] = __half2float(qtr[j]);
        q1[i] = __half2float(qtr[448 + j]);
    }
    for (int p = w; p < 2 * NN; p += 4) {
        int n = p >> 1, h = p & 1;
        float s = 0.f;
        #pragma unroll
        for (int i = 0; i < 14; ++i) {
            float kv = __half2float(skv[n][lane + i * 32]);
            s += (h ? q1[i] : q0[i]) * kv;
        }
        #pragma unroll
        for (int o = 16; o; o >>= 1) s += __shfl_xor_sync(0xffffffffu, s, o);
        if (lane == 0) sc[h][n] = s;
    }
    __syncthreads();

    if (tid < 2) {
        int h = tid;
        float ch = __half2float(qtr[896 + h]);
        const float scale = rsqrtf(136.f);
        float v[NN];
        float mx = -3.4e38f;
        int allm = 1;
        #pragma unroll
        for (int n = 0; n < NN; n++) {
            int masked = (nbrs[kvbase + n] == 0);
            float s = masked ? -1e9f : (sc[h][n] + ch) * scale;
            if (!masked) allm = 0;
            v[n] = s;
            mx = fmaxf(mx, s);
        }
        float ssum = 0.f;
        #pragma unroll
        for (int n = 0; n < NN; n++) { float e = __expf(v[n] - mx); v[n] = e; ssum += e; }
        float inv = 1.f / ssum;
        #pragma unroll
        for (int n = 0; n < NN; n++) aw[h][n] = v[n] * inv;
        if (h == 0) AM[r] = allm;
    }
    __syncthreads();

    for (int j = tid; j < 448; j += 128) {
        float c0 = 0.f, c1 = 0.f;
        #pragma unroll
        for (int n = 0; n < NN; n++) {
            float kv = __half2float(skv[n][j]);
            c0 += aw[0][n] * kv;
            c1 += aw[1][n] * kv;
        }
        CTX[(size_t)r * CTW + j]       = __float2half(c0);
        CTX[(size_t)r * CTW + 448 + j] = __float2half(c1);
    }
}

// ---------------- host helpers ----------------
static void launch_hgemm_h(const __half* A, int lda, const __half* W, const float* bias,
                           const int* rz, __half* C, int ldc, int M, int N, int K, int relu)
{
    dim3 grid((N + 95)/96, (M + 127)/128);
    hgemm<1><<<grid, 256, HG_SMEM>>>(A, lda, W, bias, rz, (void*)C, ldc, M, N, K, relu);
}
static void launch_hgemm_f(const __half* A, int lda, const __half* W, const float* bias,
                           const int* rz, float* C, int ldc, int M, int N, int K, int relu)
{
    dim3 grid((N + 95)/96, (M + 127)/128);
    hgemm<0><<<grid, 256, HG_SMEM>>>(A, lda, W, bias, rz, (void*)C, ldc, M, N, K, relu);
}

extern "C" void kernel_launch(void* const* d_in, const int* in_sizes, int n_in,
                              void* d_out, int out_size)
{
    const float* memory = (const float*)d_in[0];
    const float* edgef  = (const float*)d_in[1];
    const int*   srcn   = (const int*)  d_in[2];
    const float* ts     = (const float*)d_in[3];
    const int*   nb1    = (const int*)  d_in[4];
    const int*   ei1    = (const int*)  d_in[5];
    const float* et1    = (const float*)d_in[6];
    const int*   nb2    = (const int*)  d_in[7];
    const int*   ei2    = (const int*)  d_in[8];
    const float* et2    = (const float*)d_in[9];
    const float* w_time = (const float*)d_in[10];
    const float* b_time = (const float*)d_in[11];
    const float* Wq = (const float*)d_in[12];
    const float* bq = (const float*)d_in[13];
    const float* Wk = (const float*)d_in[14];
    const float* bk = (const float*)d_in[15];
    const float* Wv = (const float*)d_in[16];
    const float* bv = (const float*)d_in[17];
    const float* Wo = (const float*)d_in[18];
    const float* bo = (const float*)d_in[19];
    const float* W1 = (const float*)d_in[20];
    const float* b1 = (const float*)d_in[21];
    const float* W2 = (const float*)d_in[22];
    const float* b2 = (const float*)d_in[23];
    float* out = (float*)d_out;

    __half *pMEMh, *pSRCh, *pQT, *pCTX, *pAfull, *pHh, *pEMBh;
    __half *pWqk, *pWqT, *pWc, *pWov, *pW1h, *pW2h;
    float *pbc, *pbOV, *pZero;
    int* pAM;
    cudaGetSymbolAddress((void**)&pMEMh,  g_MEMh);
    cudaGetSymbolAddress((void**)&pSRCh,  g_SRCh);
    cudaGetSymbolAddress((void**)&pQT,    g_QTh);
    cudaGetSymbolAddress((void**)&pCTX,   g_CTX);
    cudaGetSymbolAddress((void**)&pAfull, g_Afull);
    cudaGetSymbolAddress((void**)&pHh,    g_Hh);
    cudaGetSymbolAddress((void**)&pEMBh,  g_EMBh);
    cudaGetSymbolAddress((void**)&pWqk,   g_Wqk);
    cudaGetSymbolAddress((void**)&pWqT,   g_WqT);
    cudaGetSymbolAddress((void**)&pWc,    g_Wc);
    cudaGetSymbolAddress((void**)&pWov,   g_Wov);
    cudaGetSymbolAddress((void**)&pW1h,   g_W1h);
    cudaGetSymbolAddress((void**)&pW2h,   g_W2h);
    cudaGetSymbolAddress((void**)&pbc,    g_bc);
    cudaGetSymbolAddress((void**)&pbOV,   g_bOV);
    cudaGetSymbolAddress((void**)&pZero,  g_zero);
    cudaGetSymbolAddress((void**)&pAM,    g_AM);

    cudaFuncSetAttribute((const void*)hgemm<1>, cudaFuncAttributeMaxDynamicSharedMemorySize, HG_SMEM);
    cudaFuncSetAttribute((const void*)hgemm<0>, cudaFuncAttributeMaxDynamicSharedMemorySize, HG_SMEM);

    const size_t WCs = (size_t)WQKR*QK, WOVs = (size_t)E_*CTW,
                 W1s = (size_t)D_*KPAD, W2s = (size_t)D_*QK,
                 WQKs = (size_t)WQKR*QTK, WQTs = (size_t)QK*QTK;

    // ---- prologue ----
    convert_all<<<dim3(512, 5), 256>>>(W1, W2, memory);                          // 1
    build_wqk<<<dim3(256, 2), 256>>>(Wk, bk);                                    // 2
    transpose_wq<<<dim3(64, 2), 256>>>(Wq);                                      // 3
    prep_qbias<<<dim3(10, 2), 256>>>(Wq, bq, b_time, Wo, bv, bo);                // 4
    // Wc[l] = Wqk[l] @ WqT[l]^T  (tensor cores; M=904, N=192, K=288)
    launch_hgemm_h(pWqk, QTK, pWqT, pZero, nullptr, pWc, QK, WQKR, QK, QTK, 0);  // 5a
    launch_hgemm_h(pWqk + WQKs, QTK, pWqT + WQTs, pZero, nullptr,
                   pWc + WCs, QK, WQKR, QK, QTK, 0);                             // 5b
    build_wov<<<dim3(E_, 2, 2), 128>>>(Wo, Wv);                                  // 6

    // ================= Layer 1 =================
    gather16<<<(R1*24 + 255)/256, 256>>>(nb1, pSRCh, R1);                        // 7
    launch_hgemm_h(pSRCh, QK, pWc, pbc, nullptr, pQT, QTW, R1, QTN, QK, 0);      // 8
    fused_attn<1><<<R1, 128>>>(pMEMh, QK, nb2, edgef, ei2, et2, ts, NN,          // 9
                               w_time, b_time, pQT, pCTX, pAM, R1);
    launch_hgemm_h(pCTX, CTW, pWov, pbOV, pAM, pAfull, KPAD, R1, E_, CTW, 0);    // 10
    copy_src<<<(R1*D_ + 255)/256, 256>>>(R1);                                    // 11
    launch_hgemm_h(pAfull, KPAD, pW1h, b1, nullptr, pHh, QK, R1, D_, KPAD, 1);   // 12
    launch_hgemm_h(pHh, QK, pW2h, b2, nullptr, pEMBh, D_, R1, D_, QK, 0);        // 13

    // ================= Layer 2 =================
    gather16<<<(NB*24 + 255)/256, 256>>>(srcn, pSRCh, NB);                       // 14
    launch_hgemm_h(pSRCh, QK, pWc + WCs, pbc + WQKR, nullptr, pQT, QTW, NB, QTN, QK, 0); // 15
    fused_attn<0><<<NB, 128>>>(pEMBh, D_, nb1, edgef, ei1, et1, ts, 1,           // 16
                               w_time, b_time, pQT, pCTX, pAM, NB);
    launch_hgemm_h(pCTX, CTW, pWov + WOVs, pbOV + E_, pAM, pAfull, KPAD, NB, E_, CTW, 0); // 17
    copy_src<<<(NB*D_ + 255)/256, 256>>>(NB);                                    // 18
    launch_hgemm_h(pAfull, KPAD, pW1h + W1s, b1 + D_, nullptr, pHh, QK, NB, D_, KPAD, 1); // 19
    launch_hgemm_f(pHh, QK, pW2h + W2s, b2 + D_, nullptr, out, D_, NB, D_, QK, 0);        // 20
}

// round 16
// speedup vs baseline: 1.0680x; 1.0531x over previous
#include <cuda_runtime.h>
#include <cuda_fp16.h>
#include <math.h>
#include <stdint.h>

// ---------------- problem constants ----------------
#define NB    1000      // B
#define NN    20        // neighbors per node
#define D_    172
#define DT_   100
#define E_    272       // D + DT
#define DK_   444       // D + DT + DE
#define KPAD  448       // padded K for W1 GEMM input
#define QK    192       // padded K (172->192); MEMh/SRCh stride; col 172 == constant 1
#define QTK   288       // per-layer K block in the Wc build GEMM
#define WCK   576       // block-diagonal K (2 layers)
#define QTW   912       // QT row stride: [q~0(448) | q~1(448) | c0 c1 | pad]
#define QTN   898       // valid QT cols
#define CTW   896       // CTX row stride: [ctx0(448) | ctx1(448)]
#define WQKR  904       // Wqk rows per layer (padded from 898)
#define NNODE 100000

#define R1    (NB*NN)    // 20000 layer-1 queries

// ---------------- scratch (device globals; zero-initialized, no allocs) ----------------
__device__ __align__(16) __half g_MEMh [(size_t)NNODE * QK];    // fp16 memory; col 172 = 1.0
__device__ __align__(16) __half g_SRCh [(size_t)R1 * QK];       // gathered src rows (incl. the 1)
__device__ __align__(16) __half g_QTh  [(size_t)R1 * QTW];      // q~ per query
__device__ __align__(16) __half g_CTX  [(size_t)R1 * CTW];      // per-head raw contexts
__device__ __align__(16) __half g_Afull[(size_t)R1 * KPAD];     // [O(272)|src(172)|pad4] MLP input
__device__ __align__(16) __half g_Hh   [(size_t)R1 * QK];       // pads stay 0
__device__ __align__(16) __half g_EMBh [(size_t)R1 * D_ + 64];
// weights
__device__ __align__(16) __half g_Wqk2 [(size_t)2 * WQKR * WCK]; // block-diagonal Wk-scatter
__device__ __align__(16) __half g_WqT2 [(size_t)QK * WCK];       // [WqT_l0 | WqT_l1]; row 172 = cq
__device__ __align__(16) __half g_Wc2  [(size_t)2 * WQKR * QK];  // folded Wqk@Wq (+bc in col 172)
__device__ __align__(16) __half g_Wov  [(size_t)2 * E_ * CTW];   // combined Wo@Wv per head
__device__ __align__(16) __half g_W1h  [(size_t)2 * D_ * KPAD];
__device__ __align__(16) __half g_W2h  [(size_t)2 * D_ * QK];
__device__ float g_bOV  [2 * E_];
__device__ float g_zero [1024];         // stays 0
__device__ int   g_AM   [R1];

// ============================================================================
// fp16 tensor-core GEMM (HMMA) -- round-12 proven config (977us baseline):
//   C[M,N] = A[M,K] @ W[N,K]^T + bias  (fp32 accum; fp16/fp32 out, relu, rowzero)
// CTA tile 128x96, BK=32, 256 thr (warps 4m x 2n, warp tile 32x48).
// 3-stage cp.async ring, ONE __syncthreads per chunk.
// ============================================================================
#define AST 40
#define BST 40
#define A_STAGE (128 * AST)
#define B_STAGE (96 * BST)
#define HG_SMEM ((3 * (A_STAGE + B_STAGE)) * 2)   // 53760 bytes

__device__ __forceinline__ void ldsm_x4(uint32_t* r, uint32_t addr) {
    asm volatile("ldmatrix.sync.aligned.m8n8.x4.shared.b16 {%0,%1,%2,%3}, [%4];"
                 : "=r"(r[0]), "=r"(r[1]), "=r"(r[2]), "=r"(r[3]) : "r"(addr));
}
__device__ __forceinline__ void mma16816(float* d, const uint32_t* a, uint32_t b0, uint32_t b1) {
    asm volatile("mma.sync.aligned.m16n8k16.row.col.f32.f16.f16.f32 "
                 "{%0,%1,%2,%3}, {%4,%5,%6,%7}, {%8,%9}, {%0,%1,%2,%3};"
                 : "+f"(d[0]), "+f"(d[1]), "+f"(d[2]), "+f"(d[3])
                 : "r"(a[0]), "r"(a[1]), "r"(a[2]), "r"(a[3]), "r"(b0), "r"(b1));
}
__device__ __forceinline__ void cp16(uint32_t dst, const void* src, int sz) {
    asm volatile("cp.async.cg.shared.global [%0], [%1], 16, %2;"
                 :: "r"(dst), "l"(src), "r"(sz));
}

template<int HALF_OUT>
__global__ __launch_bounds__(256)
void hgemm(const __half* __restrict__ A, int lda,
           const __half* __restrict__ W,
           const float* __restrict__ bias,
           const int* __restrict__ rowzero,
           void* __restrict__ Cout, int ldc,
           int M, int N, int K, int relu)
{
    extern __shared__ __half smem[];
    __half* sA = smem;
    __half* sB = smem + 3 * A_STAGE;

    const int tid  = threadIdx.x;
    const int lane = tid & 31, wid = tid >> 5;
    const int warp_m = wid & 3, warp_n = wid >> 2;
    const int m0 = blockIdx.y * 128;
    const int n0 = blockIdx.x * 96;
    const int nchunks = K >> 5;

    float acc[2][6][4];
    #pragma unroll
    for (int i = 0; i < 2; i++)
        #pragma unroll
        for (int j = 0; j < 6; j++)
            #pragma unroll
            for (int q = 0; q < 4; q++) acc[i][j][q] = 0.f;

    auto loadA = [&](int s, int k0) {
        #pragma unroll
        for (int c = tid; c < 512; c += 256) {
            int row = c >> 2, seg = c & 3;
            int gm = m0 + row;
            uint32_t dst = (uint32_t)__cvta_generic_to_shared(&sA[s * A_STAGE + row * AST + seg * 8]);
            cp16(dst, A + (size_t)gm * lda + k0 + seg * 8, gm < M ? 16 : 0);
        }
    };
    auto loadB = [&](int s, int k0) {
        #pragma unroll
        for (int c = tid; c < 384; c += 256) {
            int row = c >> 2, seg = c & 3;
            int gn = n0 + row;
            uint32_t dst = (uint32_t)__cvta_generic_to_shared(&sB[s * B_STAGE + row * BST + seg * 8]);
            cp16(dst, W + (size_t)gn * K + k0 + seg * 8, gn < N ? 16 : 0);
        }
    };

    auto computeStage = [&](int s) {
        const __half* As = sA + s * A_STAGE;
        const __half* Bs = sB + s * B_STAGE;
        #pragma unroll
        for (int kk = 0; kk < 2; ++kk) {
            uint32_t afr[2][4];
            #pragma unroll
            for (int i = 0; i < 2; ++i) {
                uint32_t addr = (uint32_t)__cvta_generic_to_shared(
                    &As[(warp_m * 32 + i * 16 + (lane & 15)) * AST + kk * 16 + (lane >> 4) * 8]);
                ldsm_x4(afr[i], addr);
            }
            uint32_t bfr[3][4];
            #pragma unroll
            for (int j = 0; j < 3; ++j) {
                int nrow = warp_n * 48 + j * 16 + ((lane >> 4) << 3) + (lane & 7);
                int kcol = kk * 16 + ((lane >> 3) & 1) * 8;
                uint32_t addr = (uint32_t)__cvta_generic_to_shared(&Bs[nrow * BST + kcol]);
                ldsm_x4(bfr[j], addr);
            }
            #pragma unroll
            for (int i = 0; i < 2; ++i)
                #pragma unroll
                for (int j = 0; j < 6; ++j)
                    mma16816(acc[i][j], afr[i], bfr[j >> 1][(j & 1) * 2], bfr[j >> 1][(j & 1) * 2 + 1]);
        }
    };

    loadA(0, 0); loadB(0, 0);
    asm volatile("cp.async.commit_group;" ::: "memory");
    if (nchunks > 1) { loadA(1, 32); loadB(1, 32); }
    asm volatile("cp.async.commit_group;" ::: "memory");

    for (int c = 0; c < nchunks; ++c) {
        asm volatile("cp.async.wait_group 1;" ::: "memory");
        __syncthreads();
        if (c + 2 < nchunks) {
            int s = (c + 2) % 3;
            loadA(s, (c + 2) * 32); loadB(s, (c + 2) * 32);
        }
        asm volatile("cp.async.commit_group;" ::: "memory");
        computeStage(c % 3);
    }

    #pragma unroll
    for (int i = 0; i < 2; ++i) {
        #pragma unroll
        for (int half_ = 0; half_ < 2; ++half_) {
            int r = m0 + warp_m * 32 + i * 16 + (lane >> 2) + half_ * 8;
            if (r >= M) continue;
            int rz = rowzero ? rowzero[r] : 0;
            #pragma unroll
            for (int j = 0; j < 6; ++j) {
                int col = n0 + warp_n * 48 + j * 8 + (lane & 3) * 2;
                if (col < N) {
                    float v0 = acc[i][j][half_ * 2]     + bias[col];
                    float v1 = acc[i][j][half_ * 2 + 1] + bias[col + 1];
                    if (rz) { v0 = 0.f; v1 = 0.f; }
                    if (relu) { v0 = fmaxf(v0, 0.f); v1 = fmaxf(v1, 0.f); }
                    if (HALF_OUT) {
                        *(__half2*)((__half*)Cout + (size_t)r * ldc + col) =
                            __floats2half2_rn(v0, v1);
                    } else {
                        float* cp = (float*)Cout + (size_t)r * ldc + col;
                        cp[0] = v0; cp[1] = v1;
                    }
                }
            }
        }
    }
}

// ---------------- fused conversion: W1, W2 -> fp16 padded; memory -> MEMh (col172=1) ----
struct CvtJob { int srcSel; long srcOff; long N; int Ksrc; int Kcopy; int KP; int oneCol; int dstSel; long dstOff; };
__constant__ CvtJob c_jobs[5] = {
    {0, 0,            D_,    DK_, DK_, KPAD, -1,  0, 0},
    {0, (long)D_*DK_, D_,    DK_, DK_, KPAD, -1,  0, (long)D_*KPAD},
    {1, 0,            D_,    D_,  D_,  QK,   -1,  1, 0},
    {1, (long)D_*D_,  D_,    D_,  D_,  QK,   -1,  1, (long)D_*QK},
    {2, 0,            NNODE, D_,  D_,  QK,   172, 2, 0},
};

__global__ void convert_all(const float* __restrict__ W1, const float* __restrict__ W2,
                            const float* __restrict__ mem)
{
    CvtJob j = c_jobs[blockIdx.y];
    const float* srcTab[3] = {W1, W2, mem};
    __half* dstTab[3] = {g_W1h, g_W2h, g_MEMh};
    const float* src = srcTab[j.srcSel] + j.srcOff;
    __half* dst = dstTab[j.dstSel] + j.dstOff;
    long total = j.N * j.KP;
    for (long i = (long)blockIdx.x * blockDim.x + threadIdx.x; i < total;
         i += (long)gridDim.x * blockDim.x) {
        int k = (int)(i % j.KP);
        long n = i / j.KP;
        float v = (k < j.Kcopy) ? src[n * j.Ksrc + k] : (k == j.oneCol ? 1.f : 0.f);
        dst[i] = __float2half(v);
    }
}

// ---------------- Wqk2: block-diagonal transpose-scatter of Wk + bk rows ----------------
// layer l occupies rows [l*904, l*904+904), cols [l*288, l*288+288); rest stays 0.
__global__ void build_wqk(const float* __restrict__ Wk, const float* __restrict__ bk)
{
    int l = blockIdx.y;
    const long total = (long)WQKR * QTK;
    for (long i = (long)blockIdx.x * blockDim.x + threadIdx.x; i < total;
         i += (long)gridDim.x * blockDim.x) {
        int n = (int)(i / QTK), k = (int)(i % QTK);
        float v = 0.f;
        if (n < 444) {
            if (k < 136) v = Wk[((size_t)l * E_ + k) * DK_ + n];
        } else if (n >= 448 && n < 892) {
            if (k >= 136 && k < E_) v = Wk[((size_t)l * E_ + k) * DK_ + (n - 448)];
        } else if (n == 896) {
            if (k < 136) v = bk[l * E_ + k];
        } else if (n == 897) {
            if (k >= 136 && k < E_) v = bk[l * E_ + k];
        }
        g_Wqk2[((size_t)l * WQKR + n) * WCK + l * QTK + k] = __float2half(v);
    }
}

// ---------------- prep_small: WqT2 transpose + cq row + bOV (all warp-parallel) ----------
// z=0: WqT2[k][l*288+e] = Wq[l][e][k] (k<172)
// z=1: WqT2[172][l*288+e] = cq[l][e] = bq + cos(b_time)·Wq[e][172:]
// z=2: bOV[l][m] = Wo[l][m]·bv[l] + bo[l][m]
__global__ void prep_small(const float* __restrict__ Wq, const float* __restrict__ bq,
                           const float* __restrict__ b_time,
                           const float* __restrict__ Wo, const float* __restrict__ bv,
                           const float* __restrict__ bo)
{
    int l = blockIdx.y;
    int tid = threadIdx.x, lane = tid & 31, w = tid >> 5;

    if (blockIdx.z == 0) {
        const long total = (long)D_ * E_;
        for (long i = (long)blockIdx.x * 256 + tid; i < total; i += 34L * 256) {
            int k = (int)(i / E_), e = (int)(i % E_);
            g_WqT2[(size_t)k * WCK + l * QTK + e] =
                __float2half(Wq[((size_t)l * E_ + e) * E_ + k]);
        }
    } else if (blockIdx.z == 1) {
        int e = blockIdx.x * 8 + w;
        if (e < E_) {
            float s = (lane == 0) ? bq[l * E_ + e] : 0.f;
            const float* wr = Wq + (size_t)l * E_ * E_ + (size_t)e * E_ + D_;
            for (int j = lane; j < DT_; j += 32) s += cosf(b_time[j]) * wr[j];
            #pragma unroll
            for (int o = 16; o; o >>= 1) s += __shfl_xor_sync(0xffffffffu, s, o);
            if (lane == 0)
                g_WqT2[(size_t)172 * WCK + l * QTK + e] = __float2half(s);
        }
    } else {
        int m = blockIdx.x * 8 + w;
        if (m < E_) {
            const float* wo = Wo + ((size_t)l * E_ + m) * E_;
            float s = 0.f;
            for (int e = lane; e < E_; e += 32) s += wo[e] * bv[l * E_ + e];
            #pragma unroll
            for (int o = 16; o; o >>= 1) s += __shfl_xor_sync(0xffffffffu, s, o);
            if (lane == 0) g_bOV[l * E_ + m] = s + bo[l * E_ + m];
        }
    }
}

// ---------------- Wov[l][m][h*448+j] = sum_d Wo[l][m][h*136+d] * Wv[l][h*136+d][j] ----
__global__ void build_wov(const float* __restrict__ Wo, const float* __restrict__ Wv)
{
    int m = blockIdx.x, h = blockIdx.y, l = blockIdx.z;
    __shared__ float wo[136];
    for (int d = threadIdx.x; d < 136; d += 128)
        wo[d] = Wo[((size_t)l * E_ + m) * E_ + h * 136 + d];
    __syncthreads();
    for (int j = threadIdx.x; j < 448; j += 128) {
        float s = 0.f;
        if (j < 444) {
            const float* wv = Wv + ((size_t)l * E_ + h * 136) * DK_ + j;
            #pragma unroll 4
            for (int d = 0; d < 136; d++) s += wo[d] * wv[(size_t)d * DK_];
        }
        g_Wov[((size_t)l * E_ + m) * CTW + h * 448 + j] = __float2half(s);
    }
}

// ---------------- fp16 row gather from g_MEMh (both stride QK) ----------------
__global__ void gather16(const int* __restrict__ idx, __half* __restrict__ dst, int rows)
{
    long total = (long)rows * 24;
    for (long i = (long)blockIdx.x*blockDim.x + threadIdx.x; i < total;
         i += (long)gridDim.x * blockDim.x) {
        int r = (int)(i / 24);
        int s = (int)(i % 24);
        ((uint4*)(dst + (size_t)r * QK))[s] =
            ((const uint4*)(g_MEMh + (size_t)idx[r] * QK))[s];
    }
}

// ---------------- copy SRC rows into MLP-input cols [272, 444) ----------------
__global__ void copy_src(int rows)
{
    long total = (long)rows * D_;
    for (long i = (long)blockIdx.x*blockDim.x + threadIdx.x; i < total;
         i += (long)gridDim.x * blockDim.x) {
        int r = (int)(i / D_);
        int k = (int)(i % D_);
        g_Afull[(size_t)r * KPAD + E_ + k] = g_SRCh[(size_t)r * QK + k];
    }
}

// ============================================================================
// fused attention (round-12 proven): block per query.
// ============================================================================
template<int GATHER>
__global__ __launch_bounds__(128)
void fused_attn(const __half* __restrict__ memh, int mstride,
                const int* __restrict__ nbrs,
                const float* __restrict__ edgef,
                const int* __restrict__ eidx,
                const float* __restrict__ etime,
                const float* __restrict__ ts, int ts_div,
                const float* __restrict__ w_time, const float* __restrict__ b_time,
                const __half* __restrict__ QT,
                __half* __restrict__ CTX, int* __restrict__ AM, int R)
{
    __shared__ __half skv[NN][448];
    __shared__ float sc[2][NN];
    __shared__ float aw[2][NN];

    int r = blockIdx.x;
    if (r >= R) return;
    int tid = threadIdx.x, lane = tid & 31, w = tid >> 5;
    float tsr = ts[r / ts_div];
    const long kvbase = (long)r * NN;

    for (int idx = tid; idx < NN * 448; idx += 128) {
        int n = idx / 448, j = idx - n * 448;
        long kvrow = kvbase + n;
        float v;
        if (j < D_) {
            long src = GATHER ? (long)nbrs[kvrow] : kvrow;
            v = __half2float(memh[src * mstride + j]);
        } else if (j < E_) {
            int q = j - D_;
            float dt = tsr - etime[kvrow];
            v = __cosf(dt * w_time[q] + b_time[q]);
        } else if (j < DK_) {
            v = edgef[(size_t)eidx[kvrow] * D_ + (j - E_)];
        } else v = 0.f;
        skv[n][j] = __float2half(v);
    }
    __syncthreads();

    const __half* qtr = QT + (size_t)r * QTW;
    float q0[14], q1[14];
    #pragma unroll
    for (int i = 0; i < 14; ++i) {
        int j = lane + i * 32;
        q0[i] = __half2float(qtr[j]);
        q1[i] = __half2float(qtr[448 + j]);
    }
    for (int p = w; p < 2 * NN; p += 4) {
        int n = p >> 1, h = p & 1;
        float s = 0.f;
        #pragma unroll
        for (int i = 0; i < 14; ++i) {
            float kv = __half2float(skv[n][lane + i * 32]);
            s += (h ? q1[i] : q0[i]) * kv;
        }
        #pragma unroll
        for (int o = 16; o; o >>= 1) s += __shfl_xor_sync(0xffffffffu, s, o);
        if (lane == 0) sc[h][n] = s;
    }
    __syncthreads();

    if (tid < 2) {
        int h = tid;
        float ch = __half2float(qtr[896 + h]);
        const float scale = rsqrtf(136.f);
        float v[NN];
        float mx = -3.4e38f;
        int allm = 1;
        #pragma unroll
        for (int n = 0; n < NN; n++) {
            int masked = (nbrs[kvbase + n] == 0);
            float s = masked ? -1e9f : (sc[h][n] + ch) * scale;
            if (!masked) allm = 0;
            v[n] = s;
            mx = fmaxf(mx, s);
        }
        float ssum = 0.f;
        #pragma unroll
        for (int n = 0; n < NN; n++) { float e = __expf(v[n] - mx); v[n] = e; ssum += e; }
        float inv = 1.f / ssum;
        #pragma unroll
        for (int n = 0; n < NN; n++) aw[h][n] = v[n] * inv;
        if (h == 0) AM[r] = allm;
    }
    __syncthreads();

    for (int j = tid; j < 448; j += 128) {
        float c0 = 0.f, c1 = 0.f;
        #pragma unroll
        for (int n = 0; n < NN; n++) {
            float kv = __half2float(skv[n][j]);
            c0 += aw[0][n] * kv;
            c1 += aw[1][n] * kv;
        }
        CTX[(size_t)r * CTW + j]       = __float2half(c0);
        CTX[(size_t)r * CTW + 448 + j] = __float2half(c1);
    }
}

// ---------------- host helpers ----------------
static void launch_hgemm_h(const __half* A, int lda, const __half* W, const float* bias,
                           const int* rz, __half* C, int ldc, int M, int N, int K, int relu)
{
    dim3 grid((N + 95)/96, (M + 127)/128);
    hgemm<1><<<grid, 256, HG_SMEM>>>(A, lda, W, bias, rz, (void*)C, ldc, M, N, K, relu);
}
static void launch_hgemm_f(const __half* A, int lda, const __half* W, const float* bias,
                           const int* rz, float* C, int ldc, int M, int N, int K, int relu)
{
    dim3 grid((N + 95)/96, (M + 127)/128);
    hgemm<0><<<grid, 256, HG_SMEM>>>(A, lda, W, bias, rz, (void*)C, ldc, M, N, K, relu);
}

extern "C" void kernel_launch(void* const* d_in, const int* in_sizes, int n_in,
                              void* d_out, int out_size)
{
    const float* memory = (const float*)d_in[0];
    const float* edgef  = (const float*)d_in[1];
    const int*   srcn   = (const int*)  d_in[2];
    const float* ts     = (const float*)d_in[3];
    const int*   nb1    = (const int*)  d_in[4];
    const int*   ei1    = (const int*)  d_in[5];
    const float* et1    = (const float*)d_in[6];
    const int*   nb2    = (const int*)  d_in[7];
    const int*   ei2    = (const int*)  d_in[8];
    const float* et2    = (const float*)d_in[9];
    const float* w_time = (const float*)d_in[10];
    const float* b_time = (const float*)d_in[11];
    const float* Wq = (const float*)d_in[12];
    const float* bq = (const float*)d_in[13];
    const float* Wk = (const float*)d_in[14];
    const float* bk = (const float*)d_in[15];
    const float* Wv = (const float*)d_in[16];
    const float* bv = (const float*)d_in[17];
    const float* Wo = (const float*)d_in[18];
    const float* bo = (const float*)d_in[19];
    const float* W1 = (const float*)d_in[20];
    const float* b1 = (const float*)d_in[21];
    const float* W2 = (const float*)d_in[22];
    const float* b2 = (const float*)d_in[23];
    float* out = (float*)d_out;

    __half *pMEMh, *pSRCh, *pQT, *pCTX, *pAfull, *pHh, *pEMBh;
    __half *pWqk2, *pWqT2, *pWc2, *pWov, *pW1h, *pW2h;
    float *pbOV, *pZero;
    int* pAM;
    cudaGetSymbolAddress((void**)&pMEMh,  g_MEMh);
    cudaGetSymbolAddress((void**)&pSRCh,  g_SRCh);
    cudaGetSymbolAddress((void**)&pQT,    g_QTh);
    cudaGetSymbolAddress((void**)&pCTX,   g_CTX);
    cudaGetSymbolAddress((void**)&pAfull, g_Afull);
    cudaGetSymbolAddress((void**)&pHh,    g_Hh);
    cudaGetSymbolAddress((void**)&pEMBh,  g_EMBh);
    cudaGetSymbolAddress((void**)&pWqk2,  g_Wqk2);
    cudaGetSymbolAddress((void**)&pWqT2,  g_WqT2);
    cudaGetSymbolAddress((void**)&pWc2,   g_Wc2);
    cudaGetSymbolAddress((void**)&pWov,   g_Wov);
    cudaGetSymbolAddress((void**)&pW1h,   g_W1h);
    cudaGetSymbolAddress((void**)&pW2h,   g_W2h);
    cudaGetSymbolAddress((void**)&pbOV,   g_bOV);
    cudaGetSymbolAddress((void**)&pZero,  g_zero);
    cudaGetSymbolAddress((void**)&pAM,    g_AM);

    cudaFuncSetAttribute((const void*)hgemm<1>, cudaFuncAttributeMaxDynamicSharedMemorySize, HG_SMEM);
    cudaFuncSetAttribute((const void*)hgemm<0>, cudaFuncAttributeMaxDynamicSharedMemorySize, HG_SMEM);

    const size_t WCs = (size_t)WQKR*QK, WOVs = (size_t)E_*CTW,
                 W1s = (size_t)D_*KPAD, W2s = (size_t)D_*QK;

    // ---- prologue ----
    convert_all<<<dim3(512, 5), 256>>>(W1, W2, memory);                          // 1
    build_wqk<<<dim3(256, 2), 256>>>(Wk, bk);                                    // 2
    prep_small<<<dim3(34, 2, 3), 256>>>(Wq, bq, b_time, Wo, bv, bo);             // 3
    // Wc2 = Wqk2 @ WqT2^T  (block-diagonal; both layers in one GEMM)
    launch_hgemm_h(pWqk2, WCK, pWqT2, pZero, nullptr, pWc2, QK, 2*WQKR, QK, WCK, 0); // 4

    // ================= Layer 1 =================
    gather16<<<(R1*24 + 255)/256, 256>>>(nb1, pSRCh, R1);                        // 5
    launch_hgemm_h(pSRCh, QK, pWc2, pZero, nullptr, pQT, QTW, R1, QTN, QK, 0);   // 6 <- profiled
    build_wov<<<dim3(E_, 2, 2), 128>>>(Wo, Wv);                                  // 7
    fused_attn<1><<<R1, 128>>>(pMEMh, QK, nb2, edgef, ei2, et2, ts, NN,          // 8
                               w_time, b_time, pQT, pCTX, pAM, R1);
    launch_hgemm_h(pCTX, CTW, pWov, pbOV, pAM, pAfull, KPAD, R1, E_, CTW, 0);    // 9
    copy_src<<<(R1*D_ + 255)/256, 256>>>(R1);                                    // 10
    launch_hgemm_h(pAfull, KPAD, pW1h, b1, nullptr, pHh, QK, R1, D_, KPAD, 1);   // 11
    launch_hgemm_h(pHh, QK, pW2h, b2, nullptr, pEMBh, D_, R1, D_, QK, 0);        // 12

    // ================= Layer 2 =================
    gather16<<<(NB*24 + 255)/256, 256>>>(srcn, pSRCh, NB);                       // 13
    launch_hgemm_h(pSRCh, QK, pWc2 + WCs, pZero, nullptr, pQT, QTW, NB, QTN, QK, 0); // 14
    fused_attn<0><<<NB, 128>>>(pEMBh, D_, nb1, edgef, ei1, et1, ts, 1,           // 15
                               w_time, b_time, pQT, pCTX, pAM, NB);
    launch_hgemm_h(pCTX, CTW, pWov + WOVs, pbOV + E_, pAM, pAfull, KPAD, NB, E_, CTW, 0); // 16
    copy_src<<<(NB*D_ + 255)/256, 256>>>(NB);                                    // 17
    launch_hgemm_h(pAfull, KPAD, pW1h + W1s, b1 + D_, nullptr, pHh, QK, NB, D_, KPAD, 1); // 18
    launch_hgemm_f(pHh, QK, pW2h + W2s, b2 + D_, nullptr, out, D_, NB, D_, QK, 0);        // 19
}

// round 17
// speedup vs baseline: 1.5007x; 1.4051x over previous
#include <cuda_runtime.h>
#include <cuda_fp16.h>
#include <math.h>
#include <stdint.h>

// ---------------- problem constants ----------------
#define NB    1000      // B
#define NN    20        // neighbors per node
#define D_    172
#define DT_   100
#define E_    272       // D + DT
#define DK_   444       // D + DT + DE
#define KPAD  448       // padded K for W1 GEMM input
#define QK    192       // padded K (172->192); MEMh/SRCh stride; col 172 == constant 1
#define QTK   288       // per-layer K block in the Wc build GEMM
#define WCK   576       // block-diagonal K (2 layers)
#define QTW   912       // QT row stride: [q~0(448) | q~1(448) | c0 c1 | pad]
#define QTN   898       // valid QT cols
#define CTW   896       // CTX row stride: [ctx0(448) | ctx1(448)]
#define WQKR  904       // Wqk rows per layer (padded from 898)
#define NNODE 100000

#define R1    (NB*NN)    // 20000 layer-1 queries

// ---------------- scratch (device globals; zero-initialized, no allocs) ----------------
__device__ __align__(16) __half g_MEMh [(size_t)NNODE * QK];    // fp16 memory; col 172 = 1.0
__device__ __align__(16) __half g_SRCh [(size_t)R1 * QK];       // gathered src rows (incl. the 1)
__device__ __align__(16) __half g_QTh  [(size_t)R1 * QTW];      // q~ per query
__device__ __align__(16) __half g_CTX  [(size_t)R1 * CTW];      // per-head raw contexts
__device__ __align__(16) __half g_Afull[(size_t)R1 * KPAD];     // [O(272)|src(172)|pad4] MLP input
__device__ __align__(16) __half g_Hh   [(size_t)R1 * QK];       // pads stay 0
__device__ __align__(16) __half g_EMBh [(size_t)R1 * D_ + 64];
// weights
__device__ __align__(16) __half g_Wqk2 [(size_t)2 * WQKR * WCK]; // block-diagonal Wk-scatter
__device__ __align__(16) __half g_WqT2 [(size_t)QK * WCK];       // [WqT_l0 | WqT_l1]; row 172 = cq
__device__ __align__(16) __half g_Wc2  [(size_t)2 * WQKR * QK];  // folded Wqk@Wq (+bc in col 172)
__device__ __align__(16) __half g_Wov  [(size_t)2 * E_ * CTW];   // combined Wo@Wv per head
__device__ __align__(16) __half g_W1h  [(size_t)2 * D_ * KPAD];
__device__ __align__(16) __half g_W2h  [(size_t)2 * D_ * QK];
__device__ float g_bOV  [2 * E_];
__device__ float g_zero [1024];         // stays 0
__device__ int   g_AM   [R1];

// ============================================================================
// fp16 tensor-core GEMM (HMMA) -- proven config:
//   C[M,N] = A[M,K] @ W[N,K]^T + bias  (fp32 accum; fp16/fp32 out, relu, rowzero)
// CTA tile 128x96, BK=32, 256 thr (warps 4m x 2n, warp tile 32x48).
// 3-stage cp.async ring, ONE __syncthreads per chunk.
// ============================================================================
#define AST 40
#define BST 40
#define A_STAGE (128 * AST)
#define B_STAGE (96 * BST)
#define HG_SMEM ((3 * (A_STAGE + B_STAGE)) * 2)   // 53760 bytes

__device__ __forceinline__ void ldsm_x4(uint32_t* r, uint32_t addr) {
    asm volatile("ldmatrix.sync.aligned.m8n8.x4.shared.b16 {%0,%1,%2,%3}, [%4];"
                 : "=r"(r[0]), "=r"(r[1]), "=r"(r[2]), "=r"(r[3]) : "r"(addr));
}
__device__ __forceinline__ void mma16816(float* d, const uint32_t* a, uint32_t b0, uint32_t b1) {
    asm volatile("mma.sync.aligned.m16n8k16.row.col.f32.f16.f16.f32 "
                 "{%0,%1,%2,%3}, {%4,%5,%6,%7}, {%8,%9}, {%0,%1,%2,%3};"
                 : "+f"(d[0]), "+f"(d[1]), "+f"(d[2]), "+f"(d[3])
                 : "r"(a[0]), "r"(a[1]), "r"(a[2]), "r"(a[3]), "r"(b0), "r"(b1));
}
__device__ __forceinline__ void cp16(uint32_t dst, const void* src, int sz) {
    asm volatile("cp.async.cg.shared.global [%0], [%1], 16, %2;"
                 :: "r"(dst), "l"(src), "r"(sz));
}

template<int HALF_OUT>
__global__ __launch_bounds__(256)
void hgemm(const __half* __restrict__ A, int lda,
           const __half* __restrict__ W,
           const float* __restrict__ bias,
           const int* __restrict__ rowzero,
           void* __restrict__ Cout, int ldc,
           int M, int N, int K, int relu)
{
    extern __shared__ __half smem[];
    __half* sA = smem;
    __half* sB = smem + 3 * A_STAGE;

    const int tid  = threadIdx.x;
    const int lane = tid & 31, wid = tid >> 5;
    const int warp_m = wid & 3, warp_n = wid >> 2;
    const int m0 = blockIdx.y * 128;
    const int n0 = blockIdx.x * 96;
    const int nchunks = K >> 5;

    float acc[2][6][4];
    #pragma unroll
    for (int i = 0; i < 2; i++)
        #pragma unroll
        for (int j = 0; j < 6; j++)
            #pragma unroll
            for (int q = 0; q < 4; q++) acc[i][j][q] = 0.f;

    auto loadA = [&](int s, int k0) {
        #pragma unroll
        for (int c = tid; c < 512; c += 256) {
            int row = c >> 2, seg = c & 3;
            int gm = m0 + row;
            uint32_t dst = (uint32_t)__cvta_generic_to_shared(&sA[s * A_STAGE + row * AST + seg * 8]);
            cp16(dst, A + (size_t)gm * lda + k0 + seg * 8, gm < M ? 16 : 0);
        }
    };
    auto loadB = [&](int s, int k0) {
        #pragma unroll
        for (int c = tid; c < 384; c += 256) {
            int row = c >> 2, seg = c & 3;
            int gn = n0 + row;
            uint32_t dst = (uint32_t)__cvta_generic_to_shared(&sB[s * B_STAGE + row * BST + seg * 8]);
            cp16(dst, W + (size_t)gn * K + k0 + seg * 8, gn < N ? 16 : 0);
        }
    };

    auto computeStage = [&](int s) {
        const __half* As = sA + s * A_STAGE;
        const __half* Bs = sB + s * B_STAGE;
        #pragma unroll
        for (int kk = 0; kk < 2; ++kk) {
            uint32_t afr[2][4];
            #pragma unroll
            for (int i = 0; i < 2; ++i) {
                uint32_t addr = (uint32_t)__cvta_generic_to_shared(
                    &As[(warp_m * 32 + i * 16 + (lane & 15)) * AST + kk * 16 + (lane >> 4) * 8]);
                ldsm_x4(afr[i], addr);
            }
            uint32_t bfr[3][4];
            #pragma unroll
            for (int j = 0; j < 3; ++j) {
                int nrow = warp_n * 48 + j * 16 + ((lane >> 4) << 3) + (lane & 7);
                int kcol = kk * 16 + ((lane >> 3) & 1) * 8;
                uint32_t addr = (uint32_t)__cvta_generic_to_shared(&Bs[nrow * BST + kcol]);
                ldsm_x4(bfr[j], addr);
            }
            #pragma unroll
            for (int i = 0; i < 2; ++i)
                #pragma unroll
                for (int j = 0; j < 6; ++j)
                    mma16816(acc[i][j], afr[i], bfr[j >> 1][(j & 1) * 2], bfr[j >> 1][(j & 1) * 2 + 1]);
        }
    };

    loadA(0, 0); loadB(0, 0);
    asm volatile("cp.async.commit_group;" ::: "memory");
    if (nchunks > 1) { loadA(1, 32); loadB(1, 32); }
    asm volatile("cp.async.commit_group;" ::: "memory");

    for (int c = 0; c < nchunks; ++c) {
        asm volatile("cp.async.wait_group 1;" ::: "memory");
        __syncthreads();
        if (c + 2 < nchunks) {
            int s = (c + 2) % 3;
            loadA(s, (c + 2) * 32); loadB(s, (c + 2) * 32);
        }
        asm volatile("cp.async.commit_group;" ::: "memory");
        computeStage(c % 3);
    }

    #pragma unroll
    for (int i = 0; i < 2; ++i) {
        #pragma unroll
        for (int half_ = 0; half_ < 2; ++half_) {
            int r = m0 + warp_m * 32 + i * 16 + (lane >> 2) + half_ * 8;
            if (r >= M) continue;
            int rz = rowzero ? rowzero[r] : 0;
            #pragma unroll
            for (int j = 0; j < 6; ++j) {
                int col = n0 + warp_n * 48 + j * 8 + (lane & 3) * 2;
                if (col < N) {
                    float v0 = acc[i][j][half_ * 2]     + bias[col];
                    float v1 = acc[i][j][half_ * 2 + 1] + bias[col + 1];
                    if (rz) { v0 = 0.f; v1 = 0.f; }
                    if (relu) { v0 = fmaxf(v0, 0.f); v1 = fmaxf(v1, 0.f); }
                    if (HALF_OUT) {
                        *(__half2*)((__half*)Cout + (size_t)r * ldc + col) =
                            __floats2half2_rn(v0, v1);
                    } else {
                        float* cp = (float*)Cout + (size_t)r * ldc + col;
                        cp[0] = v0; cp[1] = v1;
                    }
                }
            }
        }
    }
}

// ---------------- fused conversion: W1, W2 -> fp16 padded; memory -> MEMh (col172=1) ----
struct CvtJob { int srcSel; long srcOff; long N; int Ksrc; int Kcopy; int KP; int oneCol; int dstSel; long dstOff; };
__constant__ CvtJob c_jobs[5] = {
    {0, 0,            D_,    DK_, DK_, KPAD, -1,  0, 0},
    {0, (long)D_*DK_, D_,    DK_, DK_, KPAD, -1,  0, (long)D_*KPAD},
    {1, 0,            D_,    D_,  D_,  QK,   -1,  1, 0},
    {1, (long)D_*D_,  D_,    D_,  D_,  QK,   -1,  1, (long)D_*QK},
    {2, 0,            NNODE, D_,  D_,  QK,   172, 2, 0},
};

__global__ void convert_all(const float* __restrict__ W1, const float* __restrict__ W2,
                            const float* __restrict__ mem)
{
    CvtJob j = c_jobs[blockIdx.y];
    const float* srcTab[3] = {W1, W2, mem};
    __half* dstTab[3] = {g_W1h, g_W2h, g_MEMh};
    const float* src = srcTab[j.srcSel] + j.srcOff;
    __half* dst = dstTab[j.dstSel] + j.dstOff;
    long total = j.N * j.KP;
    for (long i = (long)blockIdx.x * blockDim.x + threadIdx.x; i < total;
         i += (long)gridDim.x * blockDim.x) {
        int k = (int)(i % j.KP);
        long n = i / j.KP;
        float v = (k < j.Kcopy) ? src[n * j.Ksrc + k] : (k == j.oneCol ? 1.f : 0.f);
        dst[i] = __float2half(v);
    }
}

// ---------------- Wqk2: block-diagonal transpose-scatter of Wk + bk rows ----------------
__global__ void build_wqk(const float* __restrict__ Wk, const float* __restrict__ bk)
{
    int l = blockIdx.y;
    const long total = (long)WQKR * QTK;
    for (long i = (long)blockIdx.x * blockDim.x + threadIdx.x; i < total;
         i += (long)gridDim.x * blockDim.x) {
        int n = (int)(i / QTK), k = (int)(i % QTK);
        float v = 0.f;
        if (n < 444) {
            if (k < 136) v = Wk[((size_t)l * E_ + k) * DK_ + n];
        } else if (n >= 448 && n < 892) {
            if (k >= 136 && k < E_) v = Wk[((size_t)l * E_ + k) * DK_ + (n - 448)];
        } else if (n == 896) {
            if (k < 136) v = bk[l * E_ + k];
        } else if (n == 897) {
            if (k >= 136 && k < E_) v = bk[l * E_ + k];
        }
        g_Wqk2[((size_t)l * WQKR + n) * WCK + l * QTK + k] = __float2half(v);
    }
}

// ---------------- prep_small: WqT2 transpose + cq row + bOV (all warp-parallel) ----------
__global__ void prep_small(const float* __restrict__ Wq, const float* __restrict__ bq,
                           const float* __restrict__ b_time,
                           const float* __restrict__ Wo, const float* __restrict__ bv,
                           const float* __restrict__ bo)
{
    int l = blockIdx.y;
    int tid = threadIdx.x, lane = tid & 31, w = tid >> 5;

    if (blockIdx.z == 0) {
        const long total = (long)D_ * E_;
        for (long i = (long)blockIdx.x * 256 + tid; i < total; i += 34L * 256) {
            int k = (int)(i / E_), e = (int)(i % E_);
            g_WqT2[(size_t)k * WCK + l * QTK + e] =
                __float2half(Wq[((size_t)l * E_ + e) * E_ + k]);
        }
    } else if (blockIdx.z == 1) {
        int e = blockIdx.x * 8 + w;
        if (e < E_) {
            float s = (lane == 0) ? bq[l * E_ + e] : 0.f;
            const float* wr = Wq + (size_t)l * E_ * E_ + (size_t)e * E_ + D_;
            for (int j = lane; j < DT_; j += 32) s += cosf(b_time[j]) * wr[j];
            #pragma unroll
            for (int o = 16; o; o >>= 1) s += __shfl_xor_sync(0xffffffffu, s, o);
            if (lane == 0)
                g_WqT2[(size_t)172 * WCK + l * QTK + e] = __float2half(s);
        }
    } else {
        int m = blockIdx.x * 8 + w;
        if (m < E_) {
            const float* wo = Wo + ((size_t)l * E_ + m) * E_;
            float s = 0.f;
            for (int e = lane; e < E_; e += 32) s += wo[e] * bv[l * E_ + e];
            #pragma unroll
            for (int o = 16; o; o >>= 1) s += __shfl_xor_sync(0xffffffffu, s, o);
            if (lane == 0) g_bOV[l * E_ + m] = s + bo[l * E_ + m];
        }
    }
}

// ---------------- Wov[l][m][h*448+j] = sum_d Wo[l][m][h*136+d] * Wv[l][h*136+d][j] ----
__global__ void build_wov(const float* __restrict__ Wo, const float* __restrict__ Wv)
{
    int m = blockIdx.x, h = blockIdx.y, l = blockIdx.z;
    __shared__ float wo[136];
    for (int d = threadIdx.x; d < 136; d += 128)
        wo[d] = Wo[((size_t)l * E_ + m) * E_ + h * 136 + d];
    __syncthreads();
    for (int j = threadIdx.x; j < 448; j += 128) {
        float s = 0.f;
        if (j < 444) {
            const float* wv = Wv + ((size_t)l * E_ + h * 136) * DK_ + j;
            #pragma unroll 4
            for (int d = 0; d < 136; d++) s += wo[d] * wv[(size_t)d * DK_];
        }
        g_Wov[((size_t)l * E_ + m) * CTW + h * 448 + j] = __float2half(s);
    }
}

// ---------------- gather_dual: MEMh[idx[r]] -> SRCh[r] (192h) AND Afull[r][272:444] ----
__global__ void gather_dual(const int* __restrict__ idx, int rows)
{
    long total = (long)rows * 96;   // 96 half2 per row
    for (long i = (long)blockIdx.x*blockDim.x + threadIdx.x; i < total;
         i += (long)gridDim.x * blockDim.x) {
        int r = (int)(i / 96);
        int s = (int)(i % 96);
        __half2 v = ((const __half2*)(g_MEMh + (size_t)idx[r] * QK))[s];
        ((__half2*)(g_SRCh + (size_t)r * QK))[s] = v;
        if (s < 86)
            *(__half2*)(g_Afull + (size_t)r * KPAD + E_ + 2*s) = v;
    }
}

// ============================================================================
// fused attention, half2-vectorized: block per query.
// kv = [mem(172) | cos(100) | edge(172) | pad4], all region bounds even.
// ============================================================================
template<int GATHER>
__global__ __launch_bounds__(128)
void fused_attn(const __half* __restrict__ memh, int mstride,
                const int* __restrict__ nbrs,
                const float* __restrict__ edgef,
                const int* __restrict__ eidx,
                const float* __restrict__ etime,
                const float* __restrict__ ts, int ts_div,
                const float* __restrict__ w_time, const float* __restrict__ b_time,
                const __half* __restrict__ QT,
                __half* __restrict__ CTX, int* __restrict__ AM, int R)
{
    __shared__ __align__(4) __half skv[NN][448];
    __shared__ float sc[2][NN];
    __shared__ float aw[2][NN];
    __shared__ float sdt[NN];
    __shared__ int   sei[NN];
    __shared__ int   snb[NN];

    int r = blockIdx.x;
    if (r >= R) return;
    int tid = threadIdx.x, lane = tid & 31, w = tid >> 5;
    const long kvbase = (long)r * NN;

    // stage per-neighbor scalars
    if (tid < NN) {
        sdt[tid] = ts[r / ts_div] - etime[kvbase + tid];
        sei[tid] = eidx[kvbase + tid];
        snb[tid] = GATHER ? nbrs[kvbase + tid] : 0;
    }
    __syncthreads();

    // Phase A: build kv tile (half2 everywhere)
    // mem region: 20 rows x 86 half2
    for (int p = tid; p < NN * 86; p += 128) {
        int n = p / 86, i = p - n * 86;
        long src = GATHER ? (long)snb[n] : (kvbase + n);
        *(__half2*)&skv[n][2*i] = *(const __half2*)(memh + src * mstride + 2*i);
    }
    // cos region: 20 rows x 50 half2 (cols 172..271)
    for (int p = tid; p < NN * 50; p += 128) {
        int n = p / 50, i = p - n * 50;
        int q = 2 * i;
        float dt = sdt[n];
        float a = __cosf(dt * w_time[q]   + b_time[q]);
        float b = __cosf(dt * w_time[q+1] + b_time[q+1]);
        *(__half2*)&skv[n][172 + q] = __floats2half2_rn(a, b);
    }
    // edge region: 20 rows x 86 half2 (cols 272..443), float2 loads
    for (int p = tid; p < NN * 86; p += 128) {
        int n = p / 86, i = p - n * 86;
        float2 e = *(const float2*)(edgef + (size_t)sei[n] * D_ + 2*i);
        *(__half2*)&skv[n][272 + 2*i] = __floats2half2_rn(e.x, e.y);
    }
    // pad cols 444..447
    if (tid < NN * 2) {
        int n = tid >> 1, i = tid & 1;
        *(__half2*)&skv[n][444 + 2*i] = __floats2half2_rn(0.f, 0.f);
    }
    __syncthreads();

    // Phase B: scores; q regs as float2[7] per head
    const __half2* qtr2 = (const __half2*)(QT + (size_t)r * QTW);
    float2 q0[7], q1[7];
    #pragma unroll
    for (int i = 0; i < 7; ++i) {
        q0[i] = __half22float2(qtr2[lane + i * 32]);
        q1[i] = __half22float2(qtr2[224 + lane + i * 32]);
    }
    for (int p = w; p < 2 * NN; p += 4) {
        int n = p >> 1, h = p & 1;
        const __half2* kr = (const __half2*)&skv[n][0];
        float s = 0.f;
        #pragma unroll
        for (int i = 0; i < 7; ++i) {
            float2 kv = __half22float2(kr[lane + i * 32]);
            float2 qq = h ? q1[i] : q0[i];
            s += qq.x * kv.x + qq.y * kv.y;
        }
        #pragma unroll
        for (int o = 16; o; o >>= 1) s += __shfl_xor_sync(0xffffffffu, s, o);
        if (lane == 0) sc[h][n] = s;
    }
    __syncthreads();

    // Phase C: masked softmax per head (threads 0,1)
    if (tid < 2) {
        int h = tid;
        float ch = __half2float(QT[(size_t)r * QTW + 896 + h]);
        const float scale = rsqrtf(136.f);
        float v[NN];
        float mx = -3.4e38f;
        int allm = 1;
        #pragma unroll
        for (int n = 0; n < NN; n++) {
            int masked = GATHER ? (snb[n] == 0) : (nbrs[kvbase + n] == 0);
            float s = masked ? -1e9f : (sc[h][n] + ch) * scale;
            if (!masked) allm = 0;
            v[n] = s;
            mx = fmaxf(mx, s);
        }
        float ssum = 0.f;
        #pragma unroll
        for (int n = 0; n < NN; n++) { float e = __expf(v[n] - mx); v[n] = e; ssum += e; }
        float inv = 1.f / ssum;
        #pragma unroll
        for (int n = 0; n < NN; n++) aw[h][n] = v[n] * inv;
        if (h == 0) AM[r] = allm;
    }
    __syncthreads();

    // Phase D: per-head context aggregation (half2 cols)
    __half2* ctx2 = (__half2*)(CTX + (size_t)r * CTW);
    for (int c = tid; c < 224; c += 128) {
        float c0x = 0.f, c0y = 0.f, c1x = 0.f, c1y = 0.f;
        #pragma unroll
        for (int n = 0; n < NN; n++) {
            float2 kv = __half22float2(*(const __half2*)&skv[n][2*c]);
            c0x += aw[0][n] * kv.x; c0y += aw[0][n] * kv.y;
            c1x += aw[1][n] * kv.x; c1y += aw[1][n] * kv.y;
        }
        ctx2[c]       = __floats2half2_rn(c0x, c0y);
        ctx2[224 + c] = __floats2half2_rn(c1x, c1y);
    }
}

// ---------------- host helpers ----------------
static void launch_hgemm_h(const __half* A, int lda, const __half* W, const float* bias,
                           const int* rz, __half* C, int ldc, int M, int N, int K, int relu)
{
    dim3 grid((N + 95)/96, (M + 127)/128);
    hgemm<1><<<grid, 256, HG_SMEM>>>(A, lda, W, bias, rz, (void*)C, ldc, M, N, K, relu);
}
static void launch_hgemm_f(const __half* A, int lda, const __half* W, const float* bias,
                           const int* rz, float* C, int ldc, int M, int N, int K, int relu)
{
    dim3 grid((N + 95)/96, (M + 127)/128);
    hgemm<0><<<grid, 256, HG_SMEM>>>(A, lda, W, bias, rz, (void*)C, ldc, M, N, K, relu);
}

extern "C" void kernel_launch(void* const* d_in, const int* in_sizes, int n_in,
                              void* d_out, int out_size)
{
    const float* memory = (const float*)d_in[0];
    const float* edgef  = (const float*)d_in[1];
    const int*   srcn   = (const int*)  d_in[2];
    const float* ts     = (const float*)d_in[3];
    const int*   nb1    = (const int*)  d_in[4];
    const int*   ei1    = (const int*)  d_in[5];
    const float* et1    = (const float*)d_in[6];
    const int*   nb2    = (const int*)  d_in[7];
    const int*   ei2    = (const int*)  d_in[8];
    const float* et2    = (const float*)d_in[9];
    const float* w_time = (const float*)d_in[10];
    const float* b_time = (const float*)d_in[11];
    const float* Wq = (const float*)d_in[12];
    const float* bq = (const float*)d_in[13];
    const float* Wk = (const float*)d_in[14];
    const float* bk = (const float*)d_in[15];
    const float* Wv = (const float*)d_in[16];
    const float* bv = (const float*)d_in[17];
    const float* Wo = (const float*)d_in[18];
    const float* bo = (const float*)d_in[19];
    const float* W1 = (const float*)d_in[20];
    const float* b1 = (const float*)d_in[21];
    const float* W2 = (const float*)d_in[22];
    const float* b2 = (const float*)d_in[23];
    float* out = (float*)d_out;

    __half *pMEMh, *pSRCh, *pQT, *pCTX, *pAfull, *pHh, *pEMBh;
    __half *pWqk2, *pWqT2, *pWc2, *pWov, *pW1h, *pW2h;
    float *pbOV, *pZero;
    int* pAM;
    cudaGetSymbolAddress((void**)&pMEMh,  g_MEMh);
    cudaGetSymbolAddress((void**)&pSRCh,  g_SRCh);
    cudaGetSymbolAddress((void**)&pQT,    g_QTh);
    cudaGetSymbolAddress((void**)&pCTX,   g_CTX);
    cudaGetSymbolAddress((void**)&pAfull, g_Afull);
    cudaGetSymbolAddress((void**)&pHh,    g_Hh);
    cudaGetSymbolAddress((void**)&pEMBh,  g_EMBh);
    cudaGetSymbolAddress((void**)&pWqk2,  g_Wqk2);
    cudaGetSymbolAddress((void**)&pWqT2,  g_WqT2);
    cudaGetSymbolAddress((void**)&pWc2,   g_Wc2);
    cudaGetSymbolAddress((void**)&pWov,   g_Wov);
    cudaGetSymbolAddress((void**)&pW1h,   g_W1h);
    cudaGetSymbolAddress((void**)&pW2h,   g_W2h);
    cudaGetSymbolAddress((void**)&pbOV,   g_bOV);
    cudaGetSymbolAddress((void**)&pZero,  g_zero);
    cudaGetSymbolAddress((void**)&pAM,    g_AM);

    cudaFuncSetAttribute((const void*)hgemm<1>, cudaFuncAttributeMaxDynamicSharedMemorySize, HG_SMEM);
    cudaFuncSetAttribute((const void*)hgemm<0>, cudaFuncAttributeMaxDynamicSharedMemorySize, HG_SMEM);

    const size_t WCs = (size_t)WQKR*QK, WOVs = (size_t)E_*CTW,
                 W1s = (size_t)D_*KPAD, W2s = (size_t)D_*QK;

    // ---- prologue ----
    convert_all<<<dim3(512, 5), 256>>>(W1, W2, memory);                          // 1
    build_wqk<<<dim3(256, 2), 256>>>(Wk, bk);                                    // 2
    prep_small<<<dim3(34, 2, 3), 256>>>(Wq, bq, b_time, Wo, bv, bo);             // 3
    build_wov<<<dim3(E_, 2, 2), 128>>>(Wo, Wv);                                  // 4 <- profiled slot
    launch_hgemm_h(pWqk2, WCK, pWqT2, pZero, nullptr, pWc2, QK, 2*WQKR, QK, WCK, 0); // 5

    // ================= Layer 1 =================
    gather_dual<<<(R1*96 + 255)/256, 256>>>(nb1, R1);                            // 6
    launch_hgemm_h(pSRCh, QK, pWc2, pZero, nullptr, pQT, QTW, R1, QTN, QK, 0);   // 7
    fused_attn<1><<<R1, 128>>>(pMEMh, QK, nb2, edgef, ei2, et2, ts, NN,          // 8
                               w_time, b_time, pQT, pCTX, pAM, R1);
    launch_hgemm_h(pCTX, CTW, pWov, pbOV, pAM, pAfull, KPAD, R1, E_, CTW, 0);    // 9
    launch_hgemm_h(pAfull, KPAD, pW1h, b1, nullptr, pHh, QK, R1, D_, KPAD, 1);   // 10
    launch_hgemm_h(pHh, QK, pW2h, b2, nullptr, pEMBh, D_, R1, D_, QK, 0);        // 11

    // ================= Layer 2 =================
    gather_dual<<<(NB*96 + 255)/256, 256>>>(srcn, NB);                           // 12
    launch_hgemm_h(pSRCh, QK, pWc2 + WCs, pZero, nullptr, pQT, QTW, NB, QTN, QK, 0); // 13
    fused_attn<0><<<NB, 128>>>(pEMBh, D_, nb1, edgef, ei1, et1, ts, 1,           // 14
                               w_time, b_time, pQT, pCTX, pAM, NB);
    launch_hgemm_h(pCTX, CTW, pWov + WOVs, pbOV + E_, pAM, pAfull, KPAD, NB, E_, CTW, 0); // 15
    launch_hgemm_h(pAfull, KPAD, pW1h + W1s, b1 + D_, nullptr, pHh, QK, NB, D_, KPAD, 1); // 16
    launch_hgemm_f(pHh, QK, pW2h + W2s, b2 + D_, nullptr, out, D_, NB, D_, QK, 0);        // 17
}